// round 1
// baseline (speedup 1.0000x reference)
#include <cuda_runtime.h>
#include <math.h>

#define N_NODE   100000
#define N_EDGE   500000
#define IN_DIM   128
#define OUT_DIM  128
#define ATTN_DIM 64
#define N_RELTAB 401
#define N_Q      64
#define N_TAU    366

// ---------------- scratch (no allocs allowed) ----------------
__device__ float d_hsW[N_NODE * ATTN_DIM];      // hidden @ Ws           (25.6 MB)
__device__ float d_hrW[N_RELTAB * ATTN_DIM];    // rela_embed @ Wr
__device__ float d_qW[N_Q * ATTN_DIM];          // rela_embed[q_rel] @ Wqr + b
__device__ float d_tauW[N_TAU * ATTN_DIM];      // h_tau(t) @ Wtau
__device__ float d_tauTab[N_TAU * IN_DIM];      // h_tau(t)
__device__ float d_agg[N_NODE * IN_DIM];        // 51.2 MB
__device__ float d_agg_s[N_NODE * IN_DIM];      // 51.2 MB

// ---------------- zero the accumulators ----------------
__global__ void zero_kernel() {
    int i = blockIdx.x * blockDim.x + threadIdx.x;
    const int n4 = N_NODE * IN_DIM / 4;
    float4 z = make_float4(0.f, 0.f, 0.f, 0.f);
    if (i < n4) {
        reinterpret_cast<float4*>(d_agg)[i]   = z;
        reinterpret_cast<float4*>(d_agg_s)[i] = z;
    }
}

// ---------------- build the small tables ----------------
// blocks: [0,401) -> hrW ; [401,465) -> qW ; [465,831) -> tauTab + tauW
__global__ void table_kernel(const float* __restrict__ rela,
                             const int*   __restrict__ q_rel,
                             const int*   __restrict__ q_tau_p,
                             const float* __restrict__ Wr,
                             const float* __restrict__ Wqr,
                             const float* __restrict__ Wqr_b,
                             const float* __restrict__ Wtau,
                             const float* __restrict__ w_t1,
                             const float* __restrict__ b_t1,
                             const float* __restrict__ w_t2,
                             const float* __restrict__ b_t2) {
    __shared__ float s[IN_DIM];
    int b   = blockIdx.x;
    int tid = threadIdx.x;   // 128 threads

    const float* W = nullptr;
    float* outrow  = nullptr;
    bool  add_bias = false;

    if (b < N_RELTAB) {
        s[tid] = rela[(size_t)b * IN_DIM + tid];
        W = Wr; outrow = d_hrW + b * ATTN_DIM;
    } else if (b < N_RELTAB + N_Q) {
        int r = b - N_RELTAB;
        s[tid] = rela[(size_t)q_rel[r] * IN_DIM + tid];
        W = Wqr; outrow = d_qW + r * ATTN_DIM; add_bias = true;
    } else {
        int t = b - N_RELTAB - N_Q;
        float delta = (float)(t - *q_tau_p);
        float v = w_t1[tid] * delta + b_t1[tid] + sinf(w_t2[tid] * delta + b_t2[tid]);
        s[tid] = v;
        d_tauTab[(size_t)t * IN_DIM + tid] = v;
        W = Wtau; outrow = d_tauW + t * ATTN_DIM;
    }
    __syncthreads();

    if (tid < ATTN_DIM) {
        float acc = add_bias ? Wqr_b[tid] : 0.f;
        #pragma unroll 8
        for (int k = 0; k < IN_DIM; k++)
            acc = fmaf(s[k], W[k * ATTN_DIM + tid], acc);
        outrow[tid] = acc;
    }
}

// ---------------- fp32 tiled GEMM, K = 128 fixed ----------------
// C[M,BN] = A[M,128] * B[128,BN]; 256 threads, BM=128, per-thread 8 x TN tile.
template<int BN, int TN>
__global__ void sgemm_k128(const float* __restrict__ A,
                           const float* __restrict__ B,
                           float* __restrict__ C, int M) {
    constexpr int BM = 128, BK = 16, K = 128, TM = 8;
    constexpr int TX = BN / TN;   // 16
    __shared__ float As[BK][BM];  // transposed tile
    __shared__ float Bs[BK][BN];

    const int tid = threadIdx.x;      // 256
    const int tx  = tid % TX;
    const int ty  = tid / TX;
    const int row0 = blockIdx.x * BM;

    float acc[TM][TN];
    #pragma unroll
    for (int i = 0; i < TM; i++)
        #pragma unroll
        for (int j = 0; j < TN; j++) acc[i][j] = 0.f;

    for (int k0 = 0; k0 < K; k0 += BK) {
        __syncthreads();
        // A tile: 128x16 floats, float4 along K, store transposed
        #pragma unroll
        for (int i = 0; i < (BM * BK) / (256 * 4); i++) {
            int idx = tid + i * 256;
            int ar = idx >> 2;
            int ac = (idx & 3) * 4;
            float4 v = make_float4(0.f, 0.f, 0.f, 0.f);
            if (row0 + ar < M)
                v = *reinterpret_cast<const float4*>(A + (size_t)(row0 + ar) * K + k0 + ac);
            As[ac + 0][ar] = v.x; As[ac + 1][ar] = v.y;
            As[ac + 2][ar] = v.z; As[ac + 3][ar] = v.w;
        }
        // B tile: BK x BN floats
        #pragma unroll
        for (int i = 0; i < (BK * BN) / (256 * 4); i++) {
            int idx = tid + i * 256;
            int br = idx / (BN / 4);
            int bc = (idx % (BN / 4)) * 4;
            *reinterpret_cast<float4*>(&Bs[br][bc]) =
                *reinterpret_cast<const float4*>(B + (size_t)(k0 + br) * BN + bc);
        }
        __syncthreads();

        #pragma unroll
        for (int k = 0; k < BK; k++) {
            float a[TM], bb[TN];
            #pragma unroll
            for (int i = 0; i < TM; i += 4)
                *reinterpret_cast<float4*>(&a[i]) = *reinterpret_cast<float4*>(&As[k][ty * TM + i]);
            #pragma unroll
            for (int j = 0; j < TN; j += 4)
                *reinterpret_cast<float4*>(&bb[j]) = *reinterpret_cast<float4*>(&Bs[k][tx * TN + j]);
            #pragma unroll
            for (int i = 0; i < TM; i++)
                #pragma unroll
                for (int j = 0; j < TN; j++)
                    acc[i][j] = fmaf(a[i], bb[j], acc[i][j]);
        }
    }

    #pragma unroll
    for (int i = 0; i < TM; i++) {
        int r = row0 + ty * TM + i;
        if (r < M) {
            #pragma unroll
            for (int j = 0; j < TN; j += 4)
                *reinterpret_cast<float4*>(C + (size_t)r * BN + tx * TN + j) =
                    *reinterpret_cast<float4*>(&acc[i][j]);
        }
    }
}

// ---------------- per-edge kernel: one warp per edge ----------------
__global__ void edge_kernel(const int*   __restrict__ edges,
                            const float* __restrict__ hidden,
                            const float* __restrict__ rela,
                            const float* __restrict__ w_alpha,
                            const float* __restrict__ w_alpha_b,
                            const int*   __restrict__ q_tau_p) {
    int gw   = (blockIdx.x * blockDim.x + threadIdx.x) >> 5;
    int lane = threadIdx.x & 31;
    if (gw >= N_EDGE) return;

    const int* e = edges + (size_t)gw * 7;
    int r_idx = e[0];
    int rel   = e[2];
    int tau   = e[4];
    int sub   = e[5];
    int obj   = e[6];
    int t = (tau >= 0) ? tau : *q_tau_p;

    // attention: 64 dims, 2 per lane
    float2 hv = *reinterpret_cast<const float2*>(d_hsW + (size_t)sub * ATTN_DIM + lane * 2);
    float2 rv = *reinterpret_cast<const float2*>(d_hrW + rel   * ATTN_DIM + lane * 2);
    float2 qv = *reinterpret_cast<const float2*>(d_qW  + r_idx * ATTN_DIM + lane * 2);
    float2 tv = *reinterpret_cast<const float2*>(d_tauW + t    * ATTN_DIM + lane * 2);
    float2 wa = *reinterpret_cast<const float2*>(w_alpha + lane * 2);

    float ax = fmaxf(hv.x + rv.x + qv.x + tv.x, 0.f);
    float ay = fmaxf(hv.y + rv.y + qv.y + tv.y, 0.f);
    float s  = fmaf(ax, wa.x, ay * wa.y);
    #pragma unroll
    for (int o = 16; o; o >>= 1) s += __shfl_xor_sync(0xffffffffu, s, o);
    float alpha = 1.f / (1.f + expf(-(s + w_alpha_b[0])));

    // message: 128 dims, 4 per lane
    float4 hs = *reinterpret_cast<const float4*>(hidden + (size_t)sub * IN_DIM + lane * 4);
    float4 hr = *reinterpret_cast<const float4*>(rela   + (size_t)rel * IN_DIM + lane * 4);
    float4 ht = *reinterpret_cast<const float4*>(d_tauTab + (size_t)t * IN_DIM + lane * 4);

    float4 m, m1, m2;
    m.x = hs.x + hr.x + ht.x;  m.y = hs.y + hr.y + ht.y;
    m.z = hs.z + hr.z + ht.z;  m.w = hs.w + hr.w + ht.w;
    m1.x = alpha * m.x; m1.y = alpha * m.y; m1.z = alpha * m.z; m1.w = alpha * m.w;
    m2.x = m.x - m1.x;  m2.y = m.y - m1.y;  m2.z = m.z - m1.z;  m2.w = m.w - m1.w;

    float* p1 = d_agg   + (size_t)obj * IN_DIM + lane * 4;
    float* p2 = d_agg_s + (size_t)obj * IN_DIM + lane * 4;
    asm volatile("red.global.add.v4.f32 [%0], {%1,%2,%3,%4};"
                 :: "l"(p1), "f"(m1.x), "f"(m1.y), "f"(m1.z), "f"(m1.w) : "memory");
    asm volatile("red.global.add.v4.f32 [%0], {%1,%2,%3,%4};"
                 :: "l"(p2), "f"(m2.x), "f"(m2.y), "f"(m2.z), "f"(m2.w) : "memory");
}

// ---------------- host side ----------------
extern "C" void kernel_launch(void* const* d_in, const int* in_sizes, int n_in,
                              void* d_out, int out_size) {
    (void)in_sizes; (void)n_in; (void)out_size;

    const int*   q_rel     = (const int*)  d_in[1];
    const int*   q_tau     = (const int*)  d_in[2];
    const float* hidden    = (const float*)d_in[3];
    const int*   edges     = (const int*)  d_in[4];
    const float* rela      = (const float*)d_in[7];
    const float* Ws        = (const float*)d_in[8];
    const float* Wr        = (const float*)d_in[9];
    const float* Wqr       = (const float*)d_in[10];
    const float* Wqr_b     = (const float*)d_in[11];
    const float* Wtau      = (const float*)d_in[12];
    const float* w_alpha   = (const float*)d_in[13];
    const float* w_alpha_b = (const float*)d_in[14];
    const float* W_h       = (const float*)d_in[15];
    const float* W_h_s     = (const float*)d_in[16];
    const float* w_t1      = (const float*)d_in[17];
    const float* b_t1      = (const float*)d_in[18];
    const float* w_t2      = (const float*)d_in[19];
    const float* b_t2      = (const float*)d_in[20];
    float* out = (float*)d_out;

    void *p_hsW, *p_agg, *p_agg_s;
    cudaGetSymbolAddress(&p_hsW,   d_hsW);
    cudaGetSymbolAddress(&p_agg,   d_agg);
    cudaGetSymbolAddress(&p_agg_s, d_agg_s);

    // 1) zero accumulators
    {
        int n4 = N_NODE * IN_DIM / 4;
        zero_kernel<<<(n4 + 255) / 256, 256>>>();
    }
    // 2) small tables
    table_kernel<<<N_RELTAB + N_Q + N_TAU, 128>>>(rela, q_rel, q_tau, Wr, Wqr, Wqr_b,
                                                  Wtau, w_t1, b_t1, w_t2, b_t2);
    // 3) hsW = hidden @ Ws   [100000,128]x[128,64]
    int gm = (N_NODE + 127) / 128;
    sgemm_k128<64, 4><<<gm, 256>>>(hidden, Ws, (float*)p_hsW, N_NODE);
    // 4) per-edge attention + scatter
    edge_kernel<<<(N_EDGE * 32 + 255) / 256, 256>>>(edges, hidden, rela, w_alpha,
                                                    w_alpha_b, q_tau);
    // 5) output GEMMs
    sgemm_k128<128, 8><<<gm, 256>>>((const float*)p_agg,   W_h,   out,                      N_NODE);
    sgemm_k128<128, 8><<<gm, 256>>>((const float*)p_agg_s, W_h_s, out + N_NODE * OUT_DIM,   N_NODE);
}

// round 3
// speedup vs baseline: 1.1060x; 1.1060x over previous
#include <cuda_runtime.h>
#include <cuda_bf16.h>
#include <math.h>
#include <stdint.h>

#define N_NODE   100000
#define N_EDGE   500000
#define IN_DIM   128
#define OUT_DIM  128
#define ATTN_DIM 64
#define N_RELTAB 401
#define N_Q      64
#define N_TAU    366

// ---------------- scratch (no allocs allowed) ----------------
__device__ float d_hsW[N_NODE * ATTN_DIM];
__device__ float d_hrW[N_RELTAB * ATTN_DIM];
__device__ float d_qW[N_Q * ATTN_DIM];
__device__ float d_tauW[N_TAU * ATTN_DIM];
__device__ float d_tauTab[N_TAU * IN_DIM];
__device__ float d_agg[N_NODE * IN_DIM];
__device__ float d_agg_s[N_NODE * IN_DIM];

// ---------------- helpers ----------------
__device__ __forceinline__ uint32_t smem_u32(const void* p) {
    uint32_t a;
    asm("{ .reg .u64 t; cvta.to.shared.u64 t, %1; cvt.u32.u64 %0, t; }" : "=r"(a) : "l"(p));
    return a;
}

#define LDSM_X4(r0, r1, r2, r3, addr) \
    asm volatile("ldmatrix.sync.aligned.m8n8.x4.shared.b16 {%0,%1,%2,%3}, [%4];" \
                 : "=r"(r0), "=r"(r1), "=r"(r2), "=r"(r3) : "r"(addr))
#define LDSM_X2T(r0, r1, addr) \
    asm volatile("ldmatrix.sync.aligned.m8n8.x2.trans.shared.b16 {%0,%1}, [%2];" \
                 : "=r"(r0), "=r"(r1) : "r"(addr))
#define MMA16816(c, a0, a1, a2, a3, b0, b1) \
    asm volatile("mma.sync.aligned.m16n8k16.row.col.f32.bf16.bf16.f32 " \
                 "{%0,%1,%2,%3}, {%4,%5,%6,%7}, {%8,%9}, {%0,%1,%2,%3};" \
                 : "+f"((c)[0]), "+f"((c)[1]), "+f"((c)[2]), "+f"((c)[3]) \
                 : "r"(a0), "r"(a1), "r"(a2), "r"(a3), "r"(b0), "r"(b1))

// ---------------- zero the accumulators ----------------
__global__ void zero_kernel() {
    int i = blockIdx.x * blockDim.x + threadIdx.x;
    const int n4 = N_NODE * IN_DIM / 4;
    float4 z = make_float4(0.f, 0.f, 0.f, 0.f);
    if (i < n4) {
        reinterpret_cast<float4*>(d_agg)[i]   = z;
        reinterpret_cast<float4*>(d_agg_s)[i] = z;
    }
}

// ---------------- build the small tables ----------------
__global__ void table_kernel(const float* __restrict__ rela,
                             const int*   __restrict__ q_rel,
                             const int*   __restrict__ q_tau_p,
                             const float* __restrict__ Wr,
                             const float* __restrict__ Wqr,
                             const float* __restrict__ Wqr_b,
                             const float* __restrict__ Wtau,
                             const float* __restrict__ w_t1,
                             const float* __restrict__ b_t1,
                             const float* __restrict__ w_t2,
                             const float* __restrict__ b_t2) {
    __shared__ float s[IN_DIM];
    int b   = blockIdx.x;
    int tid = threadIdx.x;

    const float* W = nullptr;
    float* outrow  = nullptr;
    bool  add_bias = false;

    if (b < N_RELTAB) {
        s[tid] = rela[(size_t)b * IN_DIM + tid];
        W = Wr; outrow = d_hrW + b * ATTN_DIM;
    } else if (b < N_RELTAB + N_Q) {
        int r = b - N_RELTAB;
        s[tid] = rela[(size_t)q_rel[r] * IN_DIM + tid];
        W = Wqr; outrow = d_qW + r * ATTN_DIM; add_bias = true;
    } else {
        int t = b - N_RELTAB - N_Q;
        float delta = (float)(t - *q_tau_p);
        float v = w_t1[tid] * delta + b_t1[tid] + sinf(w_t2[tid] * delta + b_t2[tid]);
        s[tid] = v;
        d_tauTab[(size_t)t * IN_DIM + tid] = v;
        W = Wtau; outrow = d_tauW + t * ATTN_DIM;
    }
    __syncthreads();

    if (tid < ATTN_DIM) {
        float acc = add_bias ? Wqr_b[tid] : 0.f;
        #pragma unroll 8
        for (int k = 0; k < IN_DIM; k++)
            acc = fmaf(s[k], W[k * ATTN_DIM + tid], acc);
        outrow[tid] = acc;
    }
}

// ---------------- tensor-core GEMM via mma.sync (generic sm_80+ path) -----
// C[M,N] = A[M,128] @ W[128,N], split precision bf16:
//   C = Ah*Wh + Al*Wh + Ah*Wl
// 256 threads = 8 warps; warp (wm = wid>>1, wn = wid&1) computes a
// 32 x WN tile (WN = N/2). K=128 fixed.
template<int N>
__global__ void __launch_bounds__(256, 1)
mma_gemm(const float* __restrict__ A,
         const float* __restrict__ W,
         float* __restrict__ C, int M) {
    constexpr int K      = 128;
    constexpr int SA_STR = K + 8;          // bf16 elems per A row (pad 16B)
    constexpr int SB_STR = N + 8;          // bf16 elems per B row
    constexpr int OFF_AH = 0;
    constexpr int OFF_AL = OFF_AH + 128 * SA_STR * 2;
    constexpr int OFF_BH = OFF_AL + 128 * SA_STR * 2;
    constexpr int OFF_BL = OFF_BH + K * SB_STR * 2;
    constexpr int WN     = N / 2;          // warp tile cols
    constexpr int NF     = WN / 8;         // n-fragments per warp

    extern __shared__ __align__(16) char smem[];
    const uint32_t sbase = smem_u32(smem);

    const int tid  = threadIdx.x;
    const int wid  = tid >> 5;
    const int lane = tid & 31;
    const int wm   = wid >> 1;             // 0..3 -> rows wm*32
    const int wn   = wid & 1;              // 0..1 -> cols wn*WN
    const int row0 = blockIdx.x * 128;

    // ---- convert W[128][N] fp32 -> bf16 hi/lo in SMEM ----
    for (int idx = tid; idx < K * N; idx += 256) {
        int k = idx / N, n = idx % N;
        float w = W[idx];
        __nv_bfloat16 h = __float2bfloat16(w);
        __nv_bfloat16 l = __float2bfloat16(w - __bfloat162float(h));
        *reinterpret_cast<__nv_bfloat16*>(smem + OFF_BH + (k * SB_STR + n) * 2) = h;
        *reinterpret_cast<__nv_bfloat16*>(smem + OFF_BL + (k * SB_STR + n) * 2) = l;
    }

    // ---- load + split-convert A tile (128 rows x 128 cols) ----
    {
        int row  = tid >> 1;
        int half = tid & 1;
        int grow = row0 + row;
        bool valid = grow < M;
        const float4* src = reinterpret_cast<const float4*>(A + (size_t)grow * K + half * 64);
        #pragma unroll
        for (int j = 0; j < 16; j++) {
            float4 v = valid ? src[j] : make_float4(0.f, 0.f, 0.f, 0.f);
            uint32_t h01, h23, l01, l23;
            asm("cvt.rn.bf16x2.f32 %0, %1, %2;" : "=r"(h01) : "f"(v.y), "f"(v.x));
            asm("cvt.rn.bf16x2.f32 %0, %1, %2;" : "=r"(h23) : "f"(v.w), "f"(v.z));
            float r0 = v.x - __uint_as_float(h01 << 16);
            float r1 = v.y - __uint_as_float(h01 & 0xffff0000u);
            float r2 = v.z - __uint_as_float(h23 << 16);
            float r3 = v.w - __uint_as_float(h23 & 0xffff0000u);
            asm("cvt.rn.bf16x2.f32 %0, %1, %2;" : "=r"(l01) : "f"(r1), "f"(r0));
            asm("cvt.rn.bf16x2.f32 %0, %1, %2;" : "=r"(l23) : "f"(r3), "f"(r2));
            int col = half * 64 + j * 4;
            uint32_t o = (uint32_t)(row * SA_STR + col) * 2;
            *reinterpret_cast<uint32_t*>(smem + OFF_AH + o)     = h01;
            *reinterpret_cast<uint32_t*>(smem + OFF_AH + o + 4) = h23;
            *reinterpret_cast<uint32_t*>(smem + OFF_AL + o)     = l01;
            *reinterpret_cast<uint32_t*>(smem + OFF_AL + o + 4) = l23;
        }
    }
    __syncthreads();

    // ---- accumulators ----
    float acc[2][NF][4];
    #pragma unroll
    for (int mi = 0; mi < 2; mi++)
        #pragma unroll
        for (int ni = 0; ni < NF; ni++)
            #pragma unroll
            for (int j = 0; j < 4; j++) acc[mi][ni][j] = 0.f;

    const int lrow = lane & 15;            // ldmatrix A row within tile
    const int lcol = (lane >> 4) * 8;      // ldmatrix A col half
    const uint32_t b_col = (uint32_t)(wn * WN) * 2;

    // ---- phase 1: (Ah + Al) * Bh ----
    #pragma unroll
    for (int kk = 0; kk < 8; kk++) {
        uint32_t bfr[NF][2];
        #pragma unroll
        for (int ni = 0; ni < NF; ni++) {
            uint32_t addr = sbase + OFF_BH + (uint32_t)(kk * 16 + lrow) * (SB_STR * 2)
                          + b_col + (uint32_t)ni * 16;
            LDSM_X2T(bfr[ni][0], bfr[ni][1], addr);
        }
        #pragma unroll
        for (int mi = 0; mi < 2; mi++) {
            uint32_t arow = (uint32_t)(wm * 32 + mi * 16 + lrow) * (SA_STR * 2)
                          + (uint32_t)(kk * 16 + lcol) * 2;
            uint32_t ah0, ah1, ah2, ah3, al0, al1, al2, al3;
            LDSM_X4(ah0, ah1, ah2, ah3, sbase + OFF_AH + arow);
            LDSM_X4(al0, al1, al2, al3, sbase + OFF_AL + arow);
            #pragma unroll
            for (int ni = 0; ni < NF; ni++) {
                MMA16816(acc[mi][ni], ah0, ah1, ah2, ah3, bfr[ni][0], bfr[ni][1]);
                MMA16816(acc[mi][ni], al0, al1, al2, al3, bfr[ni][0], bfr[ni][1]);
            }
        }
    }
    // ---- phase 2: Ah * Bl ----
    #pragma unroll
    for (int kk = 0; kk < 8; kk++) {
        uint32_t bfr[NF][2];
        #pragma unroll
        for (int ni = 0; ni < NF; ni++) {
            uint32_t addr = sbase + OFF_BL + (uint32_t)(kk * 16 + lrow) * (SB_STR * 2)
                          + b_col + (uint32_t)ni * 16;
            LDSM_X2T(bfr[ni][0], bfr[ni][1], addr);
        }
        #pragma unroll
        for (int mi = 0; mi < 2; mi++) {
            uint32_t arow = (uint32_t)(wm * 32 + mi * 16 + lrow) * (SA_STR * 2)
                          + (uint32_t)(kk * 16 + lcol) * 2;
            uint32_t ah0, ah1, ah2, ah3;
            LDSM_X4(ah0, ah1, ah2, ah3, sbase + OFF_AH + arow);
            #pragma unroll
            for (int ni = 0; ni < NF; ni++)
                MMA16816(acc[mi][ni], ah0, ah1, ah2, ah3, bfr[ni][0], bfr[ni][1]);
        }
    }

    // ---- epilogue ----
    const int g = lane >> 2;               // 0..7
    const int t = lane & 3;                // 0..3
    #pragma unroll
    for (int mi = 0; mi < 2; mi++) {
        int r_hi = row0 + wm * 32 + mi * 16 + g;
        #pragma unroll
        for (int half = 0; half < 2; half++) {
            int r = r_hi + half * 8;
            if (r < M) {
                float* dst = C + (size_t)r * N + wn * WN + t * 2;
                #pragma unroll
                for (int ni = 0; ni < NF; ni++) {
                    float2 o = half ? make_float2(acc[mi][ni][2], acc[mi][ni][3])
                                    : make_float2(acc[mi][ni][0], acc[mi][ni][1]);
                    *reinterpret_cast<float2*>(dst + ni * 8) = o;
                }
            }
        }
    }
}

// ---------------- per-edge kernel: one warp per edge ----------------
__global__ void edge_kernel(const int*   __restrict__ edges,
                            const float* __restrict__ hidden,
                            const float* __restrict__ rela,
                            const float* __restrict__ w_alpha,
                            const float* __restrict__ w_alpha_b,
                            const int*   __restrict__ q_tau_p) {
    int gw   = (blockIdx.x * blockDim.x + threadIdx.x) >> 5;
    int lane = threadIdx.x & 31;
    if (gw >= N_EDGE) return;

    const int* e = edges + (size_t)gw * 7;
    int r_idx = e[0];
    int rel   = e[2];
    int tau   = e[4];
    int sub   = e[5];
    int obj   = e[6];
    int t = (tau >= 0) ? tau : *q_tau_p;

    float2 hv = *reinterpret_cast<const float2*>(d_hsW + (size_t)sub * ATTN_DIM + lane * 2);
    float2 rv = *reinterpret_cast<const float2*>(d_hrW + rel   * ATTN_DIM + lane * 2);
    float2 qv = *reinterpret_cast<const float2*>(d_qW  + r_idx * ATTN_DIM + lane * 2);
    float2 tv = *reinterpret_cast<const float2*>(d_tauW + t    * ATTN_DIM + lane * 2);
    float2 wa = *reinterpret_cast<const float2*>(w_alpha + lane * 2);

    float ax = fmaxf(hv.x + rv.x + qv.x + tv.x, 0.f);
    float ay = fmaxf(hv.y + rv.y + qv.y + tv.y, 0.f);
    float s  = fmaf(ax, wa.x, ay * wa.y);
    #pragma unroll
    for (int o = 16; o; o >>= 1) s += __shfl_xor_sync(0xffffffffu, s, o);
    float alpha = 1.f / (1.f + expf(-(s + w_alpha_b[0])));

    float4 hs = *reinterpret_cast<const float4*>(hidden + (size_t)sub * IN_DIM + lane * 4);
    float4 hr = *reinterpret_cast<const float4*>(rela   + (size_t)rel * IN_DIM + lane * 4);
    float4 ht = *reinterpret_cast<const float4*>(d_tauTab + (size_t)t * IN_DIM + lane * 4);

    float4 m, m1, m2;
    m.x = hs.x + hr.x + ht.x;  m.y = hs.y + hr.y + ht.y;
    m.z = hs.z + hr.z + ht.z;  m.w = hs.w + hr.w + ht.w;
    m1.x = alpha * m.x; m1.y = alpha * m.y; m1.z = alpha * m.z; m1.w = alpha * m.w;
    m2.x = m.x - m1.x;  m2.y = m.y - m1.y;  m2.z = m.z - m1.z;  m2.w = m.w - m1.w;

    float* p1 = d_agg   + (size_t)obj * IN_DIM + lane * 4;
    float* p2 = d_agg_s + (size_t)obj * IN_DIM + lane * 4;
    asm volatile("red.global.add.v4.f32 [%0], {%1,%2,%3,%4};"
                 :: "l"(p1), "f"(m1.x), "f"(m1.y), "f"(m1.z), "f"(m1.w) : "memory");
    asm volatile("red.global.add.v4.f32 [%0], {%1,%2,%3,%4};"
                 :: "l"(p2), "f"(m2.x), "f"(m2.y), "f"(m2.z), "f"(m2.w) : "memory");
}

// ---------------- host side ----------------
extern "C" void kernel_launch(void* const* d_in, const int* in_sizes, int n_in,
                              void* d_out, int out_size) {
    (void)in_sizes; (void)n_in; (void)out_size;

    const int*   q_rel     = (const int*)  d_in[1];
    const int*   q_tau     = (const int*)  d_in[2];
    const float* hidden    = (const float*)d_in[3];
    const int*   edges     = (const int*)  d_in[4];
    const float* Ws        = (const float*)d_in[8];
    const float* rela      = (const float*)d_in[7];
    const float* Wr        = (const float*)d_in[9];
    const float* Wqr       = (const float*)d_in[10];
    const float* Wqr_b     = (const float*)d_in[11];
    const float* Wtau      = (const float*)d_in[12];
    const float* w_alpha   = (const float*)d_in[13];
    const float* w_alpha_b = (const float*)d_in[14];
    const float* W_h       = (const float*)d_in[15];
    const float* W_h_s     = (const float*)d_in[16];
    const float* w_t1      = (const float*)d_in[17];
    const float* b_t1      = (const float*)d_in[18];
    const float* w_t2      = (const float*)d_in[19];
    const float* b_t2      = (const float*)d_in[20];
    float* out = (float*)d_out;

    void *p_hsW, *p_agg, *p_agg_s;
    cudaGetSymbolAddress(&p_hsW,   d_hsW);
    cudaGetSymbolAddress(&p_agg,   d_agg);
    cudaGetSymbolAddress(&p_agg_s, d_agg_s);

    // SMEM: A hi/lo = 2*128*136*2 = 69632 B; B hi/lo = 2*128*(N+8)*2
    const int SMEM128 = 69632 + 2 * 128 * 136 * 2;  // 139264
    const int SMEM64  = 69632 + 2 * 128 * 72 * 2;   // 106496
    cudaFuncSetAttribute(mma_gemm<128>, cudaFuncAttributeMaxDynamicSharedMemorySize, SMEM128);
    cudaFuncSetAttribute(mma_gemm<64>,  cudaFuncAttributeMaxDynamicSharedMemorySize, SMEM64);

    // 1) zero accumulators
    {
        int n4 = N_NODE * IN_DIM / 4;
        zero_kernel<<<(n4 + 255) / 256, 256>>>();
    }
    // 2) small tables
    table_kernel<<<N_RELTAB + N_Q + N_TAU, 128>>>(rela, q_rel, q_tau, Wr, Wqr, Wqr_b,
                                                  Wtau, w_t1, b_t1, w_t2, b_t2);
    int gm = (N_NODE + 127) / 128;  // 782
    // 3) hsW = hidden @ Ws
    mma_gemm<64><<<gm, 256, SMEM64>>>(hidden, Ws, (float*)p_hsW, N_NODE);
    // 4) per-edge attention + scatter
    edge_kernel<<<(N_EDGE * 32 + 255) / 256, 256>>>(edges, hidden, rela, w_alpha,
                                                    w_alpha_b, q_tau);
    // 5) output GEMMs
    mma_gemm<128><<<gm, 256, SMEM128>>>((const float*)p_agg,   W_h,   out, N_NODE);
    mma_gemm<128><<<gm, 256, SMEM128>>>((const float*)p_agg_s, W_h_s, out + N_NODE * OUT_DIM, N_NODE);
}

// round 4
// speedup vs baseline: 1.1958x; 1.0813x over previous
#include <cuda_runtime.h>
#include <cuda_bf16.h>
#include <math.h>
#include <stdint.h>

#define N_NODE   100000
#define N_EDGE   500000
#define IN_DIM   128
#define OUT_DIM  128
#define ATTN_DIM 64
#define N_RELTAB 401
#define N_Q      64
#define N_TAU    366

// ---------------- scratch (no allocs allowed) ----------------
__device__ float d_hsW[N_NODE * ATTN_DIM];
__device__ float d_hrW[N_RELTAB * ATTN_DIM];
__device__ float d_qW[N_Q * ATTN_DIM];
__device__ float d_tauW[N_TAU * ATTN_DIM];
__device__ float d_tauTab[N_TAU * IN_DIM];
__device__ float d_agg[N_NODE * IN_DIM];
__device__ float d_agg_s[N_NODE * IN_DIM];

// pre-converted bf16 hi/lo weight images, padded to SMEM stride
// Wh / Whs: [128][136] bf16 ; Ws: [128][72] bf16
__device__ __nv_bfloat16 d_Wh_hi[128 * 136];
__device__ __nv_bfloat16 d_Wh_lo[128 * 136];
__device__ __nv_bfloat16 d_Whs_hi[128 * 136];
__device__ __nv_bfloat16 d_Whs_lo[128 * 136];
__device__ __nv_bfloat16 d_Ws_hi[128 * 72];
__device__ __nv_bfloat16 d_Ws_lo[128 * 72];

// ---------------- helpers ----------------
__device__ __forceinline__ uint32_t smem_u32(const void* p) {
    uint32_t a;
    asm("{ .reg .u64 t; cvta.to.shared.u64 t, %1; cvt.u32.u64 %0, t; }" : "=r"(a) : "l"(p));
    return a;
}

#define LDSM_X4(r0, r1, r2, r3, addr) \
    asm volatile("ldmatrix.sync.aligned.m8n8.x4.shared.b16 {%0,%1,%2,%3}, [%4];" \
                 : "=r"(r0), "=r"(r1), "=r"(r2), "=r"(r3) : "r"(addr))
#define LDSM_X2T(r0, r1, addr) \
    asm volatile("ldmatrix.sync.aligned.m8n8.x2.trans.shared.b16 {%0,%1}, [%2];" \
                 : "=r"(r0), "=r"(r1) : "r"(addr))
#define MMA16816(c, a0, a1, a2, a3, b0, b1) \
    asm volatile("mma.sync.aligned.m16n8k16.row.col.f32.bf16.bf16.f32 " \
                 "{%0,%1,%2,%3}, {%4,%5,%6,%7}, {%8,%9}, {%0,%1,%2,%3};" \
                 : "+f"((c)[0]), "+f"((c)[1]), "+f"((c)[2]), "+f"((c)[3]) \
                 : "r"(a0), "r"(a1), "r"(a2), "r"(a3), "r"(b0), "r"(b1))

// ---------------- zero the accumulators ----------------
__global__ void zero_kernel() {
    int i = blockIdx.x * blockDim.x + threadIdx.x;
    const int n4 = N_NODE * IN_DIM / 4;
    float4 z = make_float4(0.f, 0.f, 0.f, 0.f);
    if (i < n4) {
        reinterpret_cast<float4*>(d_agg)[i]   = z;
        reinterpret_cast<float4*>(d_agg_s)[i] = z;
    }
}

// ---------------- build the small tables ----------------
__global__ void table_kernel(const float* __restrict__ rela,
                             const int*   __restrict__ q_rel,
                             const int*   __restrict__ q_tau_p,
                             const float* __restrict__ Wr,
                             const float* __restrict__ Wqr,
                             const float* __restrict__ Wqr_b,
                             const float* __restrict__ Wtau,
                             const float* __restrict__ w_t1,
                             const float* __restrict__ b_t1,
                             const float* __restrict__ w_t2,
                             const float* __restrict__ b_t2) {
    __shared__ float s[IN_DIM];
    int b   = blockIdx.x;
    int tid = threadIdx.x;

    const float* W = nullptr;
    float* outrow  = nullptr;
    bool  add_bias = false;

    if (b < N_RELTAB) {
        s[tid] = rela[(size_t)b * IN_DIM + tid];
        W = Wr; outrow = d_hrW + b * ATTN_DIM;
    } else if (b < N_RELTAB + N_Q) {
        int r = b - N_RELTAB;
        s[tid] = rela[(size_t)q_rel[r] * IN_DIM + tid];
        W = Wqr; outrow = d_qW + r * ATTN_DIM; add_bias = true;
    } else {
        int t = b - N_RELTAB - N_Q;
        float delta = (float)(t - *q_tau_p);
        float v = w_t1[tid] * delta + b_t1[tid] + sinf(w_t2[tid] * delta + b_t2[tid]);
        s[tid] = v;
        d_tauTab[(size_t)t * IN_DIM + tid] = v;
        W = Wtau; outrow = d_tauW + t * ATTN_DIM;
    }
    __syncthreads();

    if (tid < ATTN_DIM) {
        float acc = add_bias ? Wqr_b[tid] : 0.f;
        #pragma unroll 8
        for (int k = 0; k < IN_DIM; k++)
            acc = fmaf(s[k], W[k * ATTN_DIM + tid], acc);
        outrow[tid] = acc;
    }
}

// ---------------- weight prep: fp32 -> bf16 hi/lo padded images ----------
// launch <<<128, 136>>> ; block = K row
__global__ void wprep_kernel(const float* __restrict__ Wh,
                             const float* __restrict__ Whs,
                             const float* __restrict__ Ws) {
    int k = blockIdx.x;      // 0..127
    int t = threadIdx.x;     // 0..135

    float w1 = (t < 128) ? Wh[k * 128 + t]  : 0.f;
    __nv_bfloat16 h1 = __float2bfloat16(w1);
    d_Wh_hi[k * 136 + t] = h1;
    d_Wh_lo[k * 136 + t] = __float2bfloat16(w1 - __bfloat162float(h1));

    float w2 = (t < 128) ? Whs[k * 128 + t] : 0.f;
    __nv_bfloat16 h2 = __float2bfloat16(w2);
    d_Whs_hi[k * 136 + t] = h2;
    d_Whs_lo[k * 136 + t] = __float2bfloat16(w2 - __bfloat162float(h2));

    if (t < 72) {
        float w3 = (t < 64) ? Ws[k * 64 + t] : 0.f;
        __nv_bfloat16 h3 = __float2bfloat16(w3);
        d_Ws_hi[k * 72 + t] = h3;
        d_Ws_lo[k * 72 + t] = __float2bfloat16(w3 - __bfloat162float(h3));
    }
}

// ---------------- tensor-core GEMM via mma.sync, BM = 64 -----------------
// C[M,N] = A[M,128] @ W[128,N], split precision:
//   C = Ah*Wh + Al*Wh + Ah*Wl
// 256 threads = 8 warps; warp (wm = wid>>2, wn = wid&3) computes 32 x N/4.
template<int N>
__global__ void __launch_bounds__(256)
mma_gemm(const float* __restrict__ A,
         const __nv_bfloat16* __restrict__ imgBh,
         const __nv_bfloat16* __restrict__ imgBl,
         float* __restrict__ C, int M) {
    constexpr int K      = 128;
    constexpr int BM     = 64;
    constexpr int SA_STR = K + 8;                    // bf16 per A row
    constexpr int SB_STR = N + 8;                    // bf16 per B row
    constexpr int OFF_AH = 0;
    constexpr int OFF_AL = OFF_AH + BM * SA_STR * 2;
    constexpr int OFF_BH = OFF_AL + BM * SA_STR * 2;
    constexpr int OFF_BL = OFF_BH + K * SB_STR * 2;
    constexpr int WN     = N / 4;
    constexpr int NF     = WN / 8;
    constexpr int BCNT   = K * SB_STR * 2 / 16;      // int4 per B image

    extern __shared__ __align__(16) char smem[];
    const uint32_t sbase = smem_u32(smem);

    const int tid  = threadIdx.x;
    const int wid  = tid >> 5;
    const int lane = tid & 31;
    const int wm   = wid >> 2;
    const int wn   = wid & 3;
    const int row0 = blockIdx.x * BM;

    // ---- copy pre-converted W images (L2-hot) ----
    {
        const int4* sh = reinterpret_cast<const int4*>(imgBh);
        const int4* sl = reinterpret_cast<const int4*>(imgBl);
        int4* dh = reinterpret_cast<int4*>(smem + OFF_BH);
        int4* dl = reinterpret_cast<int4*>(smem + OFF_BL);
        #pragma unroll
        for (int i = tid; i < BCNT; i += 256) { dh[i] = sh[i]; dl[i] = sl[i]; }
    }

    // ---- load + split-convert A tile (64 rows x 128 cols) ----
    {
        int row = tid >> 2;
        int q   = tid & 3;
        int grow = row0 + row;
        bool valid = grow < M;
        const float4* src = reinterpret_cast<const float4*>(A + (size_t)grow * K + q * 32);
        #pragma unroll
        for (int j = 0; j < 8; j++) {
            float4 v = valid ? src[j] : make_float4(0.f, 0.f, 0.f, 0.f);
            uint32_t h01, h23, l01, l23;
            asm("cvt.rn.bf16x2.f32 %0, %1, %2;" : "=r"(h01) : "f"(v.y), "f"(v.x));
            asm("cvt.rn.bf16x2.f32 %0, %1, %2;" : "=r"(h23) : "f"(v.w), "f"(v.z));
            float r0 = v.x - __uint_as_float(h01 << 16);
            float r1 = v.y - __uint_as_float(h01 & 0xffff0000u);
            float r2 = v.z - __uint_as_float(h23 << 16);
            float r3 = v.w - __uint_as_float(h23 & 0xffff0000u);
            asm("cvt.rn.bf16x2.f32 %0, %1, %2;" : "=r"(l01) : "f"(r1), "f"(r0));
            asm("cvt.rn.bf16x2.f32 %0, %1, %2;" : "=r"(l23) : "f"(r3), "f"(r2));
            int col = q * 32 + j * 4;
            uint32_t o = (uint32_t)(row * SA_STR + col) * 2;
            *reinterpret_cast<uint32_t*>(smem + OFF_AH + o)     = h01;
            *reinterpret_cast<uint32_t*>(smem + OFF_AH + o + 4) = h23;
            *reinterpret_cast<uint32_t*>(smem + OFF_AL + o)     = l01;
            *reinterpret_cast<uint32_t*>(smem + OFF_AL + o + 4) = l23;
        }
    }
    __syncthreads();

    float acc[2][NF][4];
    #pragma unroll
    for (int mi = 0; mi < 2; mi++)
        #pragma unroll
        for (int ni = 0; ni < NF; ni++)
            #pragma unroll
            for (int j = 0; j < 4; j++) acc[mi][ni][j] = 0.f;

    const int lrow = lane & 15;
    const int lcol = (lane >> 4) * 8;
    const uint32_t b_col = (uint32_t)(wn * WN) * 2;

    // ---- phase 1: (Ah + Al) * Bh ----
    #pragma unroll
    for (int kk = 0; kk < 8; kk++) {
        uint32_t bfr[NF][2];
        #pragma unroll
        for (int ni = 0; ni < NF; ni++) {
            uint32_t addr = sbase + OFF_BH + (uint32_t)(kk * 16 + lrow) * (SB_STR * 2)
                          + b_col + (uint32_t)ni * 16;
            LDSM_X2T(bfr[ni][0], bfr[ni][1], addr);
        }
        #pragma unroll
        for (int mi = 0; mi < 2; mi++) {
            uint32_t arow = (uint32_t)(wm * 32 + mi * 16 + lrow) * (SA_STR * 2)
                          + (uint32_t)(kk * 16 + lcol) * 2;
            uint32_t ah0, ah1, ah2, ah3, al0, al1, al2, al3;
            LDSM_X4(ah0, ah1, ah2, ah3, sbase + OFF_AH + arow);
            LDSM_X4(al0, al1, al2, al3, sbase + OFF_AL + arow);
            #pragma unroll
            for (int ni = 0; ni < NF; ni++) {
                MMA16816(acc[mi][ni], ah0, ah1, ah2, ah3, bfr[ni][0], bfr[ni][1]);
                MMA16816(acc[mi][ni], al0, al1, al2, al3, bfr[ni][0], bfr[ni][1]);
            }
        }
    }
    // ---- phase 2: Ah * Bl ----
    #pragma unroll
    for (int kk = 0; kk < 8; kk++) {
        uint32_t bfr[NF][2];
        #pragma unroll
        for (int ni = 0; ni < NF; ni++) {
            uint32_t addr = sbase + OFF_BL + (uint32_t)(kk * 16 + lrow) * (SB_STR * 2)
                          + b_col + (uint32_t)ni * 16;
            LDSM_X2T(bfr[ni][0], bfr[ni][1], addr);
        }
        #pragma unroll
        for (int mi = 0; mi < 2; mi++) {
            uint32_t arow = (uint32_t)(wm * 32 + mi * 16 + lrow) * (SA_STR * 2)
                          + (uint32_t)(kk * 16 + lcol) * 2;
            uint32_t ah0, ah1, ah2, ah3;
            LDSM_X4(ah0, ah1, ah2, ah3, sbase + OFF_AH + arow);
            #pragma unroll
            for (int ni = 0; ni < NF; ni++)
                MMA16816(acc[mi][ni], ah0, ah1, ah2, ah3, bfr[ni][0], bfr[ni][1]);
        }
    }

    // ---- epilogue ----
    const int g = lane >> 2;
    const int t = lane & 3;
    #pragma unroll
    for (int mi = 0; mi < 2; mi++) {
        int r_hi = row0 + wm * 32 + mi * 16 + g;
        #pragma unroll
        for (int half = 0; half < 2; half++) {
            int r = r_hi + half * 8;
            if (r < M) {
                float* dst = C + (size_t)r * N + wn * WN + t * 2;
                #pragma unroll
                for (int ni = 0; ni < NF; ni++) {
                    float2 o = half ? make_float2(acc[mi][ni][2], acc[mi][ni][3])
                                    : make_float2(acc[mi][ni][0], acc[mi][ni][1]);
                    *reinterpret_cast<float2*>(dst + ni * 8) = o;
                }
            }
        }
    }
}

// ---------------- per-edge kernel: one warp per edge ----------------
__global__ void edge_kernel(const int*   __restrict__ edges,
                            const float* __restrict__ hidden,
                            const float* __restrict__ rela,
                            const float* __restrict__ w_alpha,
                            const float* __restrict__ w_alpha_b,
                            const int*   __restrict__ q_tau_p) {
    int gw   = (blockIdx.x * blockDim.x + threadIdx.x) >> 5;
    int lane = threadIdx.x & 31;
    if (gw >= N_EDGE) return;

    const int* e = edges + (size_t)gw * 7;
    int r_idx = e[0];
    int rel   = e[2];
    int tau   = e[4];
    int sub   = e[5];
    int obj   = e[6];
    int t = (tau >= 0) ? tau : *q_tau_p;

    float2 hv = *reinterpret_cast<const float2*>(d_hsW + (size_t)sub * ATTN_DIM + lane * 2);
    float2 rv = *reinterpret_cast<const float2*>(d_hrW + rel   * ATTN_DIM + lane * 2);
    float2 qv = *reinterpret_cast<const float2*>(d_qW  + r_idx * ATTN_DIM + lane * 2);
    float2 tv = *reinterpret_cast<const float2*>(d_tauW + t    * ATTN_DIM + lane * 2);
    float2 wa = *reinterpret_cast<const float2*>(w_alpha + lane * 2);

    float ax = fmaxf(hv.x + rv.x + qv.x + tv.x, 0.f);
    float ay = fmaxf(hv.y + rv.y + qv.y + tv.y, 0.f);
    float s  = fmaf(ax, wa.x, ay * wa.y);
    #pragma unroll
    for (int o = 16; o; o >>= 1) s += __shfl_xor_sync(0xffffffffu, s, o);
    float alpha = 1.f / (1.f + expf(-(s + w_alpha_b[0])));

    float4 hs = *reinterpret_cast<const float4*>(hidden + (size_t)sub * IN_DIM + lane * 4);
    float4 hr = *reinterpret_cast<const float4*>(rela   + (size_t)rel * IN_DIM + lane * 4);
    float4 ht = *reinterpret_cast<const float4*>(d_tauTab + (size_t)t * IN_DIM + lane * 4);

    float4 m, m1, m2;
    m.x = hs.x + hr.x + ht.x;  m.y = hs.y + hr.y + ht.y;
    m.z = hs.z + hr.z + ht.z;  m.w = hs.w + hr.w + ht.w;
    m1.x = alpha * m.x; m1.y = alpha * m.y; m1.z = alpha * m.z; m1.w = alpha * m.w;
    m2.x = m.x - m1.x;  m2.y = m.y - m1.y;  m2.z = m.z - m1.z;  m2.w = m.w - m1.w;

    float* p1 = d_agg   + (size_t)obj * IN_DIM + lane * 4;
    float* p2 = d_agg_s + (size_t)obj * IN_DIM + lane * 4;
    asm volatile("red.global.add.v4.f32 [%0], {%1,%2,%3,%4};"
                 :: "l"(p1), "f"(m1.x), "f"(m1.y), "f"(m1.z), "f"(m1.w) : "memory");
    asm volatile("red.global.add.v4.f32 [%0], {%1,%2,%3,%4};"
                 :: "l"(p2), "f"(m2.x), "f"(m2.y), "f"(m2.z), "f"(m2.w) : "memory");
}

// ---------------- host side ----------------
extern "C" void kernel_launch(void* const* d_in, const int* in_sizes, int n_in,
                              void* d_out, int out_size) {
    (void)in_sizes; (void)n_in; (void)out_size;

    const int*   q_rel     = (const int*)  d_in[1];
    const int*   q_tau     = (const int*)  d_in[2];
    const float* hidden    = (const float*)d_in[3];
    const int*   edges     = (const int*)  d_in[4];
    const float* rela      = (const float*)d_in[7];
    const float* Ws        = (const float*)d_in[8];
    const float* Wr        = (const float*)d_in[9];
    const float* Wqr       = (const float*)d_in[10];
    const float* Wqr_b     = (const float*)d_in[11];
    const float* Wtau      = (const float*)d_in[12];
    const float* w_alpha   = (const float*)d_in[13];
    const float* w_alpha_b = (const float*)d_in[14];
    const float* W_h       = (const float*)d_in[15];
    const float* W_h_s     = (const float*)d_in[16];
    const float* w_t1      = (const float*)d_in[17];
    const float* b_t1      = (const float*)d_in[18];
    const float* w_t2      = (const float*)d_in[19];
    const float* b_t2      = (const float*)d_in[20];
    float* out = (float*)d_out;

    void *p_hsW, *p_agg, *p_agg_s;
    void *p_WhH, *p_WhL, *p_WhsH, *p_WhsL, *p_WsH, *p_WsL;
    cudaGetSymbolAddress(&p_hsW,   d_hsW);
    cudaGetSymbolAddress(&p_agg,   d_agg);
    cudaGetSymbolAddress(&p_agg_s, d_agg_s);
    cudaGetSymbolAddress(&p_WhH,  d_Wh_hi);
    cudaGetSymbolAddress(&p_WhL,  d_Wh_lo);
    cudaGetSymbolAddress(&p_WhsH, d_Whs_hi);
    cudaGetSymbolAddress(&p_WhsL, d_Whs_lo);
    cudaGetSymbolAddress(&p_WsH,  d_Ws_hi);
    cudaGetSymbolAddress(&p_WsL,  d_Ws_lo);

    // SMEM: A hi/lo = 2*64*136*2 = 34816 ; B hi/lo = 2*128*(N+8)*2
    const int SMEM128 = 34816 + 2 * 128 * 136 * 2;  // 104448
    const int SMEM64  = 34816 + 2 * 128 * 72 * 2;   //  71680
    cudaFuncSetAttribute(mma_gemm<128>, cudaFuncAttributeMaxDynamicSharedMemorySize, SMEM128);
    cudaFuncSetAttribute(mma_gemm<64>,  cudaFuncAttributeMaxDynamicSharedMemorySize, SMEM64);

    // 1) zero accumulators
    {
        int n4 = N_NODE * IN_DIM / 4;
        zero_kernel<<<(n4 + 255) / 256, 256>>>();
    }
    // 2) small tables + weight images
    table_kernel<<<N_RELTAB + N_Q + N_TAU, 128>>>(rela, q_rel, q_tau, Wr, Wqr, Wqr_b,
                                                  Wtau, w_t1, b_t1, w_t2, b_t2);
    wprep_kernel<<<128, 136>>>(W_h, W_h_s, Ws);

    int gm = (N_NODE + 63) / 64;   // 1563
    // 3) hsW = hidden @ Ws
    mma_gemm<64><<<gm, 256, SMEM64>>>(hidden, (const __nv_bfloat16*)p_WsH,
                                      (const __nv_bfloat16*)p_WsL, (float*)p_hsW, N_NODE);
    // 4) per-edge attention + scatter
    edge_kernel<<<(N_EDGE * 32 + 255) / 256, 256>>>(edges, hidden, rela, w_alpha,
                                                    w_alpha_b, q_tau);
    // 5) output GEMMs
    mma_gemm<128><<<gm, 256, SMEM128>>>((const float*)p_agg,
                                        (const __nv_bfloat16*)p_WhH,
                                        (const __nv_bfloat16*)p_WhL, out, N_NODE);
    mma_gemm<128><<<gm, 256, SMEM128>>>((const float*)p_agg_s,
                                        (const __nv_bfloat16*)p_WhsH,
                                        (const __nv_bfloat16*)p_WhsL,
                                        out + N_NODE * OUT_DIM, N_NODE);
}

// round 5
// speedup vs baseline: 1.2247x; 1.0241x over previous
#include <cuda_runtime.h>
#include <cuda_bf16.h>
#include <math.h>
#include <stdint.h>

#define N_NODE   100000
#define N_EDGE   500000
#define IN_DIM   128
#define OUT_DIM  128
#define ATTN_DIM 64
#define N_RELTAB 401
#define N_Q      64
#define N_TAU    366

// ---------------- scratch (no allocs allowed) ----------------
__device__ float d_hsW[N_NODE * ATTN_DIM];
__device__ float d_hrW[N_RELTAB * ATTN_DIM];
__device__ float d_qW[N_Q * ATTN_DIM];
__device__ float d_tauW[N_TAU * ATTN_DIM];
__device__ float d_tauTab[N_TAU * IN_DIM];
__device__ float d_agg[N_NODE * IN_DIM];
__device__ float d_agg_s[N_NODE * IN_DIM];
__device__ float d_alpha[N_EDGE];

// pre-converted bf16 hi/lo weight images, padded to SMEM stride
__device__ __nv_bfloat16 d_Wh_hi[128 * 136];
__device__ __nv_bfloat16 d_Wh_lo[128 * 136];
__device__ __nv_bfloat16 d_Whs_hi[128 * 136];
__device__ __nv_bfloat16 d_Whs_lo[128 * 136];
__device__ __nv_bfloat16 d_Ws_hi[128 * 72];
__device__ __nv_bfloat16 d_Ws_lo[128 * 72];

// ---------------- helpers ----------------
__device__ __forceinline__ uint32_t smem_u32(const void* p) {
    uint32_t a;
    asm("{ .reg .u64 t; cvta.to.shared.u64 t, %1; cvt.u32.u64 %0, t; }" : "=r"(a) : "l"(p));
    return a;
}

#define LDSM_X4(r0, r1, r2, r3, addr) \
    asm volatile("ldmatrix.sync.aligned.m8n8.x4.shared.b16 {%0,%1,%2,%3}, [%4];" \
                 : "=r"(r0), "=r"(r1), "=r"(r2), "=r"(r3) : "r"(addr))
#define LDSM_X2T(r0, r1, addr) \
    asm volatile("ldmatrix.sync.aligned.m8n8.x2.trans.shared.b16 {%0,%1}, [%2];" \
                 : "=r"(r0), "=r"(r1) : "r"(addr))
#define MMA16816(c, a0, a1, a2, a3, b0, b1) \
    asm volatile("mma.sync.aligned.m16n8k16.row.col.f32.bf16.bf16.f32 " \
                 "{%0,%1,%2,%3}, {%4,%5,%6,%7}, {%8,%9}, {%0,%1,%2,%3};" \
                 : "+f"((c)[0]), "+f"((c)[1]), "+f"((c)[2]), "+f"((c)[3]) \
                 : "r"(a0), "r"(a1), "r"(a2), "r"(a3), "r"(b0), "r"(b1))

// ---------------- zero the accumulators ----------------
__global__ void zero_kernel() {
    int i = blockIdx.x * blockDim.x + threadIdx.x;
    const int n4 = N_NODE * IN_DIM / 4;
    float4 z = make_float4(0.f, 0.f, 0.f, 0.f);
    if (i < n4) {
        reinterpret_cast<float4*>(d_agg)[i]   = z;
        reinterpret_cast<float4*>(d_agg_s)[i] = z;
    }
}

// ---------------- build the small tables ----------------
__global__ void table_kernel(const float* __restrict__ rela,
                             const int*   __restrict__ q_rel,
                             const int*   __restrict__ q_tau_p,
                             const float* __restrict__ Wr,
                             const float* __restrict__ Wqr,
                             const float* __restrict__ Wqr_b,
                             const float* __restrict__ Wtau,
                             const float* __restrict__ w_t1,
                             const float* __restrict__ b_t1,
                             const float* __restrict__ w_t2,
                             const float* __restrict__ b_t2) {
    __shared__ float s[IN_DIM];
    int b   = blockIdx.x;
    int tid = threadIdx.x;

    const float* W = nullptr;
    float* outrow  = nullptr;
    bool  add_bias = false;

    if (b < N_RELTAB) {
        s[tid] = rela[(size_t)b * IN_DIM + tid];
        W = Wr; outrow = d_hrW + b * ATTN_DIM;
    } else if (b < N_RELTAB + N_Q) {
        int r = b - N_RELTAB;
        s[tid] = rela[(size_t)q_rel[r] * IN_DIM + tid];
        W = Wqr; outrow = d_qW + r * ATTN_DIM; add_bias = true;
    } else {
        int t = b - N_RELTAB - N_Q;
        float delta = (float)(t - *q_tau_p);
        float v = w_t1[tid] * delta + b_t1[tid] + sinf(w_t2[tid] * delta + b_t2[tid]);
        s[tid] = v;
        d_tauTab[(size_t)t * IN_DIM + tid] = v;
        W = Wtau; outrow = d_tauW + t * ATTN_DIM;
    }
    __syncthreads();

    if (tid < ATTN_DIM) {
        float acc = add_bias ? Wqr_b[tid] : 0.f;
        #pragma unroll 8
        for (int k = 0; k < IN_DIM; k++)
            acc = fmaf(s[k], W[k * ATTN_DIM + tid], acc);
        outrow[tid] = acc;
    }
}

// ---------------- weight prep: fp32 -> bf16 hi/lo padded images ----------
__global__ void wprep_kernel(const float* __restrict__ Wh,
                             const float* __restrict__ Whs,
                             const float* __restrict__ Ws) {
    int k = blockIdx.x;      // 0..127
    int t = threadIdx.x;     // 0..135

    float w1 = (t < 128) ? Wh[k * 128 + t]  : 0.f;
    __nv_bfloat16 h1 = __float2bfloat16(w1);
    d_Wh_hi[k * 136 + t] = h1;
    d_Wh_lo[k * 136 + t] = __float2bfloat16(w1 - __bfloat162float(h1));

    float w2 = (t < 128) ? Whs[k * 128 + t] : 0.f;
    __nv_bfloat16 h2 = __float2bfloat16(w2);
    d_Whs_hi[k * 136 + t] = h2;
    d_Whs_lo[k * 136 + t] = __float2bfloat16(w2 - __bfloat162float(h2));

    if (t < 72) {
        float w3 = (t < 64) ? Ws[k * 64 + t] : 0.f;
        __nv_bfloat16 h3 = __float2bfloat16(w3);
        d_Ws_hi[k * 72 + t] = h3;
        d_Ws_lo[k * 72 + t] = __float2bfloat16(w3 - __bfloat162float(h3));
    }
}

// ---------------- tensor-core GEMM via mma.sync, BM = 64, merged loop ----
template<int N>
__global__ void __launch_bounds__(256)
mma_gemm(const float* __restrict__ A,
         const __nv_bfloat16* __restrict__ imgBh,
         const __nv_bfloat16* __restrict__ imgBl,
         float* __restrict__ C, int M) {
    constexpr int K      = 128;
    constexpr int BM     = 64;
    constexpr int SA_STR = K + 8;
    constexpr int SB_STR = N + 8;
    constexpr int OFF_AH = 0;
    constexpr int OFF_AL = OFF_AH + BM * SA_STR * 2;
    constexpr int OFF_BH = OFF_AL + BM * SA_STR * 2;
    constexpr int OFF_BL = OFF_BH + K * SB_STR * 2;
    constexpr int WN     = N / 4;
    constexpr int NF     = WN / 8;
    constexpr int BCNT   = K * SB_STR * 2 / 16;

    extern __shared__ __align__(16) char smem[];
    const uint32_t sbase = smem_u32(smem);

    const int tid  = threadIdx.x;
    const int wid  = tid >> 5;
    const int lane = tid & 31;
    const int wm   = wid >> 2;
    const int wn   = wid & 3;
    const int row0 = blockIdx.x * BM;

    // ---- copy pre-converted W images (L2-hot) ----
    {
        const int4* sh = reinterpret_cast<const int4*>(imgBh);
        const int4* sl = reinterpret_cast<const int4*>(imgBl);
        int4* dh = reinterpret_cast<int4*>(smem + OFF_BH);
        int4* dl = reinterpret_cast<int4*>(smem + OFF_BL);
        #pragma unroll
        for (int i = tid; i < BCNT; i += 256) { dh[i] = sh[i]; dl[i] = sl[i]; }
    }

    // ---- load + split-convert A tile (64 rows x 128 cols) ----
    {
        int row = tid >> 2;
        int q   = tid & 3;
        int grow = row0 + row;
        bool valid = grow < M;
        const float4* src = reinterpret_cast<const float4*>(A + (size_t)grow * K + q * 32);
        #pragma unroll
        for (int j = 0; j < 8; j++) {
            float4 v = valid ? src[j] : make_float4(0.f, 0.f, 0.f, 0.f);
            uint32_t h01, h23, l01, l23;
            asm("cvt.rn.bf16x2.f32 %0, %1, %2;" : "=r"(h01) : "f"(v.y), "f"(v.x));
            asm("cvt.rn.bf16x2.f32 %0, %1, %2;" : "=r"(h23) : "f"(v.w), "f"(v.z));
            float r0 = v.x - __uint_as_float(h01 << 16);
            float r1 = v.y - __uint_as_float(h01 & 0xffff0000u);
            float r2 = v.z - __uint_as_float(h23 << 16);
            float r3 = v.w - __uint_as_float(h23 & 0xffff0000u);
            asm("cvt.rn.bf16x2.f32 %0, %1, %2;" : "=r"(l01) : "f"(r1), "f"(r0));
            asm("cvt.rn.bf16x2.f32 %0, %1, %2;" : "=r"(l23) : "f"(r3), "f"(r2));
            int col = q * 32 + j * 4;
            uint32_t o = (uint32_t)(row * SA_STR + col) * 2;
            *reinterpret_cast<uint32_t*>(smem + OFF_AH + o)     = h01;
            *reinterpret_cast<uint32_t*>(smem + OFF_AH + o + 4) = h23;
            *reinterpret_cast<uint32_t*>(smem + OFF_AL + o)     = l01;
            *reinterpret_cast<uint32_t*>(smem + OFF_AL + o + 4) = l23;
        }
    }
    __syncthreads();

    float acc[2][NF][4];
    #pragma unroll
    for (int mi = 0; mi < 2; mi++)
        #pragma unroll
        for (int ni = 0; ni < NF; ni++)
            #pragma unroll
            for (int j = 0; j < 4; j++) acc[mi][ni][j] = 0.f;

    const int lrow = lane & 15;
    const int lcol = (lane >> 4) * 8;
    const uint32_t b_col = (uint32_t)(wn * WN) * 2;

    // ---- merged mainloop: load fragments once, 3 MMAs each ----
    #pragma unroll
    for (int kk = 0; kk < 8; kk++) {
        uint32_t bh[NF][2], bl[NF][2];
        #pragma unroll
        for (int ni = 0; ni < NF; ni++) {
            uint32_t rowoff = (uint32_t)(kk * 16 + lrow) * (SB_STR * 2)
                            + b_col + (uint32_t)ni * 16;
            LDSM_X2T(bh[ni][0], bh[ni][1], sbase + OFF_BH + rowoff);
            LDSM_X2T(bl[ni][0], bl[ni][1], sbase + OFF_BL + rowoff);
        }
        #pragma unroll
        for (int mi = 0; mi < 2; mi++) {
            uint32_t arow = (uint32_t)(wm * 32 + mi * 16 + lrow) * (SA_STR * 2)
                          + (uint32_t)(kk * 16 + lcol) * 2;
            uint32_t ah0, ah1, ah2, ah3, al0, al1, al2, al3;
            LDSM_X4(ah0, ah1, ah2, ah3, sbase + OFF_AH + arow);
            LDSM_X4(al0, al1, al2, al3, sbase + OFF_AL + arow);
            #pragma unroll
            for (int ni = 0; ni < NF; ni++) {
                MMA16816(acc[mi][ni], ah0, ah1, ah2, ah3, bh[ni][0], bh[ni][1]);
                MMA16816(acc[mi][ni], al0, al1, al2, al3, bh[ni][0], bh[ni][1]);
                MMA16816(acc[mi][ni], ah0, ah1, ah2, ah3, bl[ni][0], bl[ni][1]);
            }
        }
    }

    // ---- epilogue ----
    const int g = lane >> 2;
    const int t = lane & 3;
    #pragma unroll
    for (int mi = 0; mi < 2; mi++) {
        int r_hi = row0 + wm * 32 + mi * 16 + g;
        #pragma unroll
        for (int half = 0; half < 2; half++) {
            int r = r_hi + half * 8;
            if (r < M) {
                float* dst = C + (size_t)r * N + wn * WN + t * 2;
                #pragma unroll
                for (int ni = 0; ni < NF; ni++) {
                    float2 o = half ? make_float2(acc[mi][ni][2], acc[mi][ni][3])
                                    : make_float2(acc[mi][ni][0], acc[mi][ni][1]);
                    *reinterpret_cast<float2*>(dst + ni * 8) = o;
                }
            }
        }
    }
}

// ---------------- alpha kernel: 2 edges per warp (16 lanes each) ---------
__global__ void alpha_kernel(const int*   __restrict__ edges,
                             const float* __restrict__ w_alpha,
                             const float* __restrict__ w_alpha_b,
                             const int*   __restrict__ q_tau_p) {
    int pw   = (blockIdx.x * blockDim.x + threadIdx.x) >> 5;
    int lane = threadIdx.x & 31;
    int eid  = pw * 2 + (lane >> 4);
    if (eid >= N_EDGE) return;
    int l = lane & 15;

    const int* e = edges + (size_t)eid * 7;
    int r_idx = e[0];
    int rel   = e[2];
    int tau   = e[4];
    int sub   = e[5];
    int t = (tau >= 0) ? tau : *q_tau_p;

    float4 hv = *reinterpret_cast<const float4*>(d_hsW + (size_t)sub * ATTN_DIM + l * 4);
    float4 rv = *reinterpret_cast<const float4*>(d_hrW + rel   * ATTN_DIM + l * 4);
    float4 qv = *reinterpret_cast<const float4*>(d_qW  + r_idx * ATTN_DIM + l * 4);
    float4 tv = *reinterpret_cast<const float4*>(d_tauW + t    * ATTN_DIM + l * 4);
    float4 wa = *reinterpret_cast<const float4*>(w_alpha + l * 4);

    float s = fmaxf(hv.x + rv.x + qv.x + tv.x, 0.f) * wa.x
            + fmaxf(hv.y + rv.y + qv.y + tv.y, 0.f) * wa.y
            + fmaxf(hv.z + rv.z + qv.z + tv.z, 0.f) * wa.z
            + fmaxf(hv.w + rv.w + qv.w + tv.w, 0.f) * wa.w;
    #pragma unroll
    for (int o = 8; o; o >>= 1) s += __shfl_xor_sync(0xffffffffu, s, o);
    if (l == 0)
        d_alpha[eid] = 1.f / (1.f + expf(-(s + w_alpha_b[0])));
}

// ---------------- scatter kernel: one 64-dim half per pass ---------------
// 2 edges per warp; lane handles 4 dims (float4 + red.v4)
template<int HALF>
__global__ void scatter_kernel(const int*   __restrict__ edges,
                               const float* __restrict__ hidden,
                               const float* __restrict__ rela,
                               const int*   __restrict__ q_tau_p) {
    int pw   = (blockIdx.x * blockDim.x + threadIdx.x) >> 5;
    int lane = threadIdx.x & 31;
    int eid  = pw * 2 + (lane >> 4);
    if (eid >= N_EDGE) return;
    int l = lane & 15;

    const int* e = edges + (size_t)eid * 7;
    int rel = e[2];
    int tau = e[4];
    int sub = e[5];
    int obj = e[6];
    int t = (tau >= 0) ? tau : *q_tau_p;
    int d = HALF * 64 + l * 4;

    float4 hs = *reinterpret_cast<const float4*>(hidden + (size_t)sub * IN_DIM + d);
    float4 hr = *reinterpret_cast<const float4*>(rela   + (size_t)rel * IN_DIM + d);
    float4 ht = *reinterpret_cast<const float4*>(d_tauTab + (size_t)t * IN_DIM + d);
    float a = d_alpha[eid];

    float4 m, m1, m2;
    m.x = hs.x + hr.x + ht.x;  m.y = hs.y + hr.y + ht.y;
    m.z = hs.z + hr.z + ht.z;  m.w = hs.w + hr.w + ht.w;
    m1.x = a * m.x; m1.y = a * m.y; m1.z = a * m.z; m1.w = a * m.w;
    m2.x = m.x - m1.x; m2.y = m.y - m1.y; m2.z = m.z - m1.z; m2.w = m.w - m1.w;

    float* p1 = d_agg   + (size_t)obj * IN_DIM + d;
    float* p2 = d_agg_s + (size_t)obj * IN_DIM + d;
    asm volatile("red.global.add.v4.f32 [%0], {%1,%2,%3,%4};"
                 :: "l"(p1), "f"(m1.x), "f"(m1.y), "f"(m1.z), "f"(m1.w) : "memory");
    asm volatile("red.global.add.v4.f32 [%0], {%1,%2,%3,%4};"
                 :: "l"(p2), "f"(m2.x), "f"(m2.y), "f"(m2.z), "f"(m2.w) : "memory");
}

// ---------------- host side ----------------
extern "C" void kernel_launch(void* const* d_in, const int* in_sizes, int n_in,
                              void* d_out, int out_size) {
    (void)in_sizes; (void)n_in; (void)out_size;

    const int*   q_rel     = (const int*)  d_in[1];
    const int*   q_tau     = (const int*)  d_in[2];
    const float* hidden    = (const float*)d_in[3];
    const int*   edges     = (const int*)  d_in[4];
    const float* rela      = (const float*)d_in[7];
    const float* Ws        = (const float*)d_in[8];
    const float* Wr        = (const float*)d_in[9];
    const float* Wqr       = (const float*)d_in[10];
    const float* Wqr_b     = (const float*)d_in[11];
    const float* Wtau      = (const float*)d_in[12];
    const float* w_alpha   = (const float*)d_in[13];
    const float* w_alpha_b = (const float*)d_in[14];
    const float* W_h       = (const float*)d_in[15];
    const float* W_h_s     = (const float*)d_in[16];
    const float* w_t1      = (const float*)d_in[17];
    const float* b_t1      = (const float*)d_in[18];
    const float* w_t2      = (const float*)d_in[19];
    const float* b_t2      = (const float*)d_in[20];
    float* out = (float*)d_out;

    void *p_hsW, *p_agg, *p_agg_s;
    void *p_WhH, *p_WhL, *p_WhsH, *p_WhsL, *p_WsH, *p_WsL;
    cudaGetSymbolAddress(&p_hsW,   d_hsW);
    cudaGetSymbolAddress(&p_agg,   d_agg);
    cudaGetSymbolAddress(&p_agg_s, d_agg_s);
    cudaGetSymbolAddress(&p_WhH,  d_Wh_hi);
    cudaGetSymbolAddress(&p_WhL,  d_Wh_lo);
    cudaGetSymbolAddress(&p_WhsH, d_Whs_hi);
    cudaGetSymbolAddress(&p_WhsL, d_Whs_lo);
    cudaGetSymbolAddress(&p_WsH,  d_Ws_hi);
    cudaGetSymbolAddress(&p_WsL,  d_Ws_lo);

    const int SMEM128 = 34816 + 2 * 128 * 136 * 2;  // 104448
    const int SMEM64  = 34816 + 2 * 128 * 72 * 2;   //  71680
    cudaFuncSetAttribute(mma_gemm<128>, cudaFuncAttributeMaxDynamicSharedMemorySize, SMEM128);
    cudaFuncSetAttribute(mma_gemm<64>,  cudaFuncAttributeMaxDynamicSharedMemorySize, SMEM64);

    // 1) zero accumulators
    {
        int n4 = N_NODE * IN_DIM / 4;
        zero_kernel<<<(n4 + 255) / 256, 256>>>();
    }
    // 2) small tables + weight images
    table_kernel<<<N_RELTAB + N_Q + N_TAU, 128>>>(rela, q_rel, q_tau, Wr, Wqr, Wqr_b,
                                                  Wtau, w_t1, b_t1, w_t2, b_t2);
    wprep_kernel<<<128, 136>>>(W_h, W_h_s, Ws);

    int gm = (N_NODE + 63) / 64;   // 1563
    // 3) hsW = hidden @ Ws
    mma_gemm<64><<<gm, 256, SMEM64>>>(hidden, (const __nv_bfloat16*)p_WsH,
                                      (const __nv_bfloat16*)p_WsL, (float*)p_hsW, N_NODE);
    // 4) attention alphas (L2-resident working set)
    int nwarp = (N_EDGE + 1) / 2;                       // 250000 warps
    int nblk  = (nwarp * 32 + 255) / 256;               // 31250 blocks
    alpha_kernel<<<nblk, 256>>>(edges, w_alpha, w_alpha_b, q_tau);
    // 5) scatter, 64 dims per pass (working set fits L2)
    scatter_kernel<0><<<nblk, 256>>>(edges, hidden, rela, q_tau);
    scatter_kernel<1><<<nblk, 256>>>(edges, hidden, rela, q_tau);
    // 6) output GEMMs
    mma_gemm<128><<<gm, 256, SMEM128>>>((const float*)p_agg,
                                        (const __nv_bfloat16*)p_WhH,
                                        (const __nv_bfloat16*)p_WhL, out, N_NODE);
    mma_gemm<128><<<gm, 256, SMEM128>>>((const float*)p_agg_s,
                                        (const __nv_bfloat16*)p_WhsH,
                                        (const __nv_bfloat16*)p_WhsL,
                                        out + N_NODE * OUT_DIM, N_NODE);
}

// round 6
// speedup vs baseline: 1.2967x; 1.0588x over previous
#include <cuda_runtime.h>
#include <cuda_bf16.h>
#include <math.h>
#include <stdint.h>

#define N_NODE   100000
#define N_EDGE   500000
#define IN_DIM   128
#define OUT_DIM  128
#define ATTN_DIM 64
#define N_RELTAB 401
#define N_Q      64
#define N_TAU    366
#define SCAN_B   1024
#define N_SCANB  ((N_NODE + SCAN_B - 1) / SCAN_B)   // 98

// ---------------- scratch (no allocs allowed) ----------------
__device__ float d_hsW[N_NODE * ATTN_DIM];
__device__ float d_hrW[N_RELTAB * ATTN_DIM];
__device__ float d_qW[N_Q * ATTN_DIM];
__device__ float d_tauW[N_TAU * ATTN_DIM];
__device__ float d_tauTab[N_TAU * IN_DIM];
__device__ float d_agg[N_NODE * IN_DIM];
__device__ float d_agg_s[N_NODE * IN_DIM];

// sort-by-obj machinery
__device__ int d_counts[N_NODE];
__device__ int d_offsets[N_NODE];
__device__ int d_cursor[N_NODE];
__device__ int d_blockSums[N_SCANB + 2];
__device__ int d_perm[N_EDGE];
__device__ int4 d_edat[N_EDGE];          // {sub, rel, t, alpha_bits}

// pre-converted bf16 hi/lo weight images, padded to SMEM stride
__device__ __nv_bfloat16 d_Wh_hi[128 * 136];
__device__ __nv_bfloat16 d_Wh_lo[128 * 136];
__device__ __nv_bfloat16 d_Whs_hi[128 * 136];
__device__ __nv_bfloat16 d_Whs_lo[128 * 136];
__device__ __nv_bfloat16 d_Ws_hi[128 * 72];
__device__ __nv_bfloat16 d_Ws_lo[128 * 72];

// ---------------- helpers ----------------
__device__ __forceinline__ uint32_t smem_u32(const void* p) {
    uint32_t a;
    asm("{ .reg .u64 t; cvta.to.shared.u64 t, %1; cvt.u32.u64 %0, t; }" : "=r"(a) : "l"(p));
    return a;
}

#define LDSM_X4(r0, r1, r2, r3, addr) \
    asm volatile("ldmatrix.sync.aligned.m8n8.x4.shared.b16 {%0,%1,%2,%3}, [%4];" \
                 : "=r"(r0), "=r"(r1), "=r"(r2), "=r"(r3) : "r"(addr))
#define LDSM_X2T(r0, r1, addr) \
    asm volatile("ldmatrix.sync.aligned.m8n8.x2.trans.shared.b16 {%0,%1}, [%2];" \
                 : "=r"(r0), "=r"(r1) : "r"(addr))
#define MMA16816(c, a0, a1, a2, a3, b0, b1) \
    asm volatile("mma.sync.aligned.m16n8k16.row.col.f32.bf16.bf16.f32 " \
                 "{%0,%1,%2,%3}, {%4,%5,%6,%7}, {%8,%9}, {%0,%1,%2,%3};" \
                 : "+f"((c)[0]), "+f"((c)[1]), "+f"((c)[2]), "+f"((c)[3]) \
                 : "r"(a0), "r"(a1), "r"(a2), "r"(a3), "r"(b0), "r"(b1))

// ---------------- build the small tables ----------------
__global__ void table_kernel(const float* __restrict__ rela,
                             const int*   __restrict__ q_rel,
                             const int*   __restrict__ q_tau_p,
                             const float* __restrict__ Wr,
                             const float* __restrict__ Wqr,
                             const float* __restrict__ Wqr_b,
                             const float* __restrict__ Wtau,
                             const float* __restrict__ w_t1,
                             const float* __restrict__ b_t1,
                             const float* __restrict__ w_t2,
                             const float* __restrict__ b_t2) {
    __shared__ float s[IN_DIM];
    int b   = blockIdx.x;
    int tid = threadIdx.x;

    const float* W = nullptr;
    float* outrow  = nullptr;
    bool  add_bias = false;

    if (b < N_RELTAB) {
        s[tid] = rela[(size_t)b * IN_DIM + tid];
        W = Wr; outrow = d_hrW + b * ATTN_DIM;
    } else if (b < N_RELTAB + N_Q) {
        int r = b - N_RELTAB;
        s[tid] = rela[(size_t)q_rel[r] * IN_DIM + tid];
        W = Wqr; outrow = d_qW + r * ATTN_DIM; add_bias = true;
    } else {
        int t = b - N_RELTAB - N_Q;
        float delta = (float)(t - *q_tau_p);
        float v = w_t1[tid] * delta + b_t1[tid] + sinf(w_t2[tid] * delta + b_t2[tid]);
        s[tid] = v;
        d_tauTab[(size_t)t * IN_DIM + tid] = v;
        W = Wtau; outrow = d_tauW + t * ATTN_DIM;
    }
    __syncthreads();

    if (tid < ATTN_DIM) {
        float acc = add_bias ? Wqr_b[tid] : 0.f;
        #pragma unroll 8
        for (int k = 0; k < IN_DIM; k++)
            acc = fmaf(s[k], W[k * ATTN_DIM + tid], acc);
        outrow[tid] = acc;
    }
}

// ---------------- weight prep ----------------
__global__ void wprep_kernel(const float* __restrict__ Wh,
                             const float* __restrict__ Whs,
                             const float* __restrict__ Ws) {
    int k = blockIdx.x;
    int t = threadIdx.x;

    float w1 = (t < 128) ? Wh[k * 128 + t]  : 0.f;
    __nv_bfloat16 h1 = __float2bfloat16(w1);
    d_Wh_hi[k * 136 + t] = h1;
    d_Wh_lo[k * 136 + t] = __float2bfloat16(w1 - __bfloat162float(h1));

    float w2 = (t < 128) ? Whs[k * 128 + t] : 0.f;
    __nv_bfloat16 h2 = __float2bfloat16(w2);
    d_Whs_hi[k * 136 + t] = h2;
    d_Whs_lo[k * 136 + t] = __float2bfloat16(w2 - __bfloat162float(h2));

    if (t < 72) {
        float w3 = (t < 64) ? Ws[k * 64 + t] : 0.f;
        __nv_bfloat16 h3 = __float2bfloat16(w3);
        d_Ws_hi[k * 72 + t] = h3;
        d_Ws_lo[k * 72 + t] = __float2bfloat16(w3 - __bfloat162float(h3));
    }
}

// ---------------- counting sort of edges by obj ----------------
__global__ void hist_zero_kernel() {
    int i = blockIdx.x * blockDim.x + threadIdx.x;
    if (i < N_NODE) d_counts[i] = 0;
}
__global__ void hist_kernel(const int* __restrict__ edges) {
    int i = blockIdx.x * blockDim.x + threadIdx.x;
    if (i < N_EDGE) atomicAdd(&d_counts[edges[(size_t)i * 7 + 6]], 1);
}
__global__ void scan1_kernel() {
    __shared__ int sh[SCAN_B];
    int gid = blockIdx.x * SCAN_B + threadIdx.x;
    int v = (gid < N_NODE) ? d_counts[gid] : 0;
    sh[threadIdx.x] = v;
    __syncthreads();
    #pragma unroll
    for (int off = 1; off < SCAN_B; off <<= 1) {
        int t = (threadIdx.x >= off) ? sh[threadIdx.x - off] : 0;
        __syncthreads();
        sh[threadIdx.x] += t;
        __syncthreads();
    }
    if (gid < N_NODE) d_offsets[gid] = sh[threadIdx.x] - v;   // exclusive
    if (threadIdx.x == SCAN_B - 1) d_blockSums[blockIdx.x] = sh[SCAN_B - 1];
}
__global__ void scan2_kernel() {
    if (threadIdx.x == 0) {
        int acc = 0;
        for (int i = 0; i < N_SCANB; i++) {
            int c = d_blockSums[i];
            d_blockSums[i] = acc;
            acc += c;
        }
    }
}
__global__ void scan3_kernel() {
    int gid = blockIdx.x * SCAN_B + threadIdx.x;
    if (gid < N_NODE) {
        int o = d_offsets[gid] + d_blockSums[gid / SCAN_B];
        d_offsets[gid] = o;
        d_cursor[gid]  = o;
    }
}
__global__ void fill_kernel(const int* __restrict__ edges) {
    int i = blockIdx.x * blockDim.x + threadIdx.x;
    if (i < N_EDGE) {
        int obj = edges[(size_t)i * 7 + 6];
        int pos = atomicAdd(&d_cursor[obj], 1);
        d_perm[pos] = i;
    }
}

// ---------------- alpha kernel: 2 edges per warp; packs edge record -----
__global__ void alpha_kernel(const int*   __restrict__ edges,
                             const float* __restrict__ w_alpha,
                             const float* __restrict__ w_alpha_b,
                             const int*   __restrict__ q_tau_p) {
    int pw   = (blockIdx.x * blockDim.x + threadIdx.x) >> 5;
    int lane = threadIdx.x & 31;
    int eid  = pw * 2 + (lane >> 4);
    if (eid >= N_EDGE) return;
    int l = lane & 15;

    const int* e = edges + (size_t)eid * 7;
    int r_idx = e[0];
    int rel   = e[2];
    int tau   = e[4];
    int sub   = e[5];
    int t = (tau >= 0) ? tau : *q_tau_p;

    float4 hv = *reinterpret_cast<const float4*>(d_hsW + (size_t)sub * ATTN_DIM + l * 4);
    float4 rv = *reinterpret_cast<const float4*>(d_hrW + rel   * ATTN_DIM + l * 4);
    float4 qv = *reinterpret_cast<const float4*>(d_qW  + r_idx * ATTN_DIM + l * 4);
    float4 tv = *reinterpret_cast<const float4*>(d_tauW + t    * ATTN_DIM + l * 4);
    float4 wa = *reinterpret_cast<const float4*>(w_alpha + l * 4);

    float s = fmaxf(hv.x + rv.x + qv.x + tv.x, 0.f) * wa.x
            + fmaxf(hv.y + rv.y + qv.y + tv.y, 0.f) * wa.y
            + fmaxf(hv.z + rv.z + qv.z + tv.z, 0.f) * wa.z
            + fmaxf(hv.w + rv.w + qv.w + tv.w, 0.f) * wa.w;
    #pragma unroll
    for (int o = 8; o; o >>= 1) s += __shfl_xor_sync(0xffffffffu, s, o);
    if (l == 0) {
        float al = 1.f / (1.f + expf(-(s + w_alpha_b[0])));
        d_edat[eid] = make_int4(sub, rel, t, __float_as_int(al));
    }
}

// ---------------- aggregation: one warp per node, register accumulation --
__global__ void __launch_bounds__(256)
agg_kernel(const float* __restrict__ hidden,
           const float* __restrict__ rela) {
    int node = (blockIdx.x * blockDim.x + threadIdx.x) >> 5;
    int lane = threadIdx.x & 31;
    if (node >= N_NODE) return;

    int start = d_offsets[node];
    int cnt   = d_counts[node];

    float4 a1 = make_float4(0.f, 0.f, 0.f, 0.f);
    float4 a2 = make_float4(0.f, 0.f, 0.f, 0.f);

    int eid = (cnt > 0) ? __ldg(&d_perm[start]) : 0;
    for (int i = 0; i < cnt; i++) {
        int4 ed = __ldg(&d_edat[eid]);
        int neid = (i + 1 < cnt) ? __ldg(&d_perm[start + i + 1]) : 0;
        float a = __int_as_float(ed.w);

        float4 hs = *reinterpret_cast<const float4*>(hidden + (size_t)ed.x * IN_DIM + lane * 4);
        float4 hr = *reinterpret_cast<const float4*>(rela   + (size_t)ed.y * IN_DIM + lane * 4);
        float4 ht = *reinterpret_cast<const float4*>(d_tauTab + (size_t)ed.z * IN_DIM + lane * 4);

        float mx = hs.x + hr.x + ht.x;
        float my = hs.y + hr.y + ht.y;
        float mz = hs.z + hr.z + ht.z;
        float mw = hs.w + hr.w + ht.w;
        a1.x = fmaf(a, mx, a1.x); a1.y = fmaf(a, my, a1.y);
        a1.z = fmaf(a, mz, a1.z); a1.w = fmaf(a, mw, a1.w);
        a2.x += mx - a * mx; a2.y += my - a * my;
        a2.z += mz - a * mz; a2.w += mw - a * mw;
        eid = neid;
    }

    *reinterpret_cast<float4*>(d_agg   + (size_t)node * IN_DIM + lane * 4) = a1;
    *reinterpret_cast<float4*>(d_agg_s + (size_t)node * IN_DIM + lane * 4) = a2;
}

// ---------------- tensor-core GEMM via mma.sync, BM = 64, merged loop ----
template<int N>
__global__ void __launch_bounds__(256)
mma_gemm(const float* __restrict__ A,
         const __nv_bfloat16* __restrict__ imgBh,
         const __nv_bfloat16* __restrict__ imgBl,
         float* __restrict__ C, int M) {
    constexpr int K      = 128;
    constexpr int BM     = 64;
    constexpr int SA_STR = K + 8;
    constexpr int SB_STR = N + 8;
    constexpr int OFF_AH = 0;
    constexpr int OFF_AL = OFF_AH + BM * SA_STR * 2;
    constexpr int OFF_BH = OFF_AL + BM * SA_STR * 2;
    constexpr int OFF_BL = OFF_BH + K * SB_STR * 2;
    constexpr int WN     = N / 4;
    constexpr int NF     = WN / 8;
    constexpr int BCNT   = K * SB_STR * 2 / 16;

    extern __shared__ __align__(16) char smem[];
    const uint32_t sbase = smem_u32(smem);

    const int tid  = threadIdx.x;
    const int wid  = tid >> 5;
    const int lane = tid & 31;
    const int wm   = wid >> 2;
    const int wn   = wid & 3;
    const int row0 = blockIdx.x * BM;

    {
        const int4* sh = reinterpret_cast<const int4*>(imgBh);
        const int4* sl = reinterpret_cast<const int4*>(imgBl);
        int4* dh = reinterpret_cast<int4*>(smem + OFF_BH);
        int4* dl = reinterpret_cast<int4*>(smem + OFF_BL);
        #pragma unroll
        for (int i = tid; i < BCNT; i += 256) { dh[i] = sh[i]; dl[i] = sl[i]; }
    }

    {
        int row = tid >> 2;
        int q   = tid & 3;
        int grow = row0 + row;
        bool valid = grow < M;
        const float4* src = reinterpret_cast<const float4*>(A + (size_t)grow * K + q * 32);
        #pragma unroll
        for (int j = 0; j < 8; j++) {
            float4 v = valid ? src[j] : make_float4(0.f, 0.f, 0.f, 0.f);
            uint32_t h01, h23, l01, l23;
            asm("cvt.rn.bf16x2.f32 %0, %1, %2;" : "=r"(h01) : "f"(v.y), "f"(v.x));
            asm("cvt.rn.bf16x2.f32 %0, %1, %2;" : "=r"(h23) : "f"(v.w), "f"(v.z));
            float r0 = v.x - __uint_as_float(h01 << 16);
            float r1 = v.y - __uint_as_float(h01 & 0xffff0000u);
            float r2 = v.z - __uint_as_float(h23 << 16);
            float r3 = v.w - __uint_as_float(h23 & 0xffff0000u);
            asm("cvt.rn.bf16x2.f32 %0, %1, %2;" : "=r"(l01) : "f"(r1), "f"(r0));
            asm("cvt.rn.bf16x2.f32 %0, %1, %2;" : "=r"(l23) : "f"(r3), "f"(r2));
            int col = q * 32 + j * 4;
            uint32_t o = (uint32_t)(row * SA_STR + col) * 2;
            *reinterpret_cast<uint32_t*>(smem + OFF_AH + o)     = h01;
            *reinterpret_cast<uint32_t*>(smem + OFF_AH + o + 4) = h23;
            *reinterpret_cast<uint32_t*>(smem + OFF_AL + o)     = l01;
            *reinterpret_cast<uint32_t*>(smem + OFF_AL + o + 4) = l23;
        }
    }
    __syncthreads();

    float acc[2][NF][4];
    #pragma unroll
    for (int mi = 0; mi < 2; mi++)
        #pragma unroll
        for (int ni = 0; ni < NF; ni++)
            #pragma unroll
            for (int j = 0; j < 4; j++) acc[mi][ni][j] = 0.f;

    const int lrow = lane & 15;
    const int lcol = (lane >> 4) * 8;
    const uint32_t b_col = (uint32_t)(wn * WN) * 2;

    #pragma unroll
    for (int kk = 0; kk < 8; kk++) {
        uint32_t bh[NF][2], bl[NF][2];
        #pragma unroll
        for (int ni = 0; ni < NF; ni++) {
            uint32_t rowoff = (uint32_t)(kk * 16 + lrow) * (SB_STR * 2)
                            + b_col + (uint32_t)ni * 16;
            LDSM_X2T(bh[ni][0], bh[ni][1], sbase + OFF_BH + rowoff);
            LDSM_X2T(bl[ni][0], bl[ni][1], sbase + OFF_BL + rowoff);
        }
        #pragma unroll
        for (int mi = 0; mi < 2; mi++) {
            uint32_t arow = (uint32_t)(wm * 32 + mi * 16 + lrow) * (SA_STR * 2)
                          + (uint32_t)(kk * 16 + lcol) * 2;
            uint32_t ah0, ah1, ah2, ah3, al0, al1, al2, al3;
            LDSM_X4(ah0, ah1, ah2, ah3, sbase + OFF_AH + arow);
            LDSM_X4(al0, al1, al2, al3, sbase + OFF_AL + arow);
            #pragma unroll
            for (int ni = 0; ni < NF; ni++) {
                MMA16816(acc[mi][ni], ah0, ah1, ah2, ah3, bh[ni][0], bh[ni][1]);
                MMA16816(acc[mi][ni], al0, al1, al2, al3, bh[ni][0], bh[ni][1]);
                MMA16816(acc[mi][ni], ah0, ah1, ah2, ah3, bl[ni][0], bl[ni][1]);
            }
        }
    }

    const int g = lane >> 2;
    const int t = lane & 3;
    #pragma unroll
    for (int mi = 0; mi < 2; mi++) {
        int r_hi = row0 + wm * 32 + mi * 16 + g;
        #pragma unroll
        for (int half = 0; half < 2; half++) {
            int r = r_hi + half * 8;
            if (r < M) {
                float* dst = C + (size_t)r * N + wn * WN + t * 2;
                #pragma unroll
                for (int ni = 0; ni < NF; ni++) {
                    float2 o = half ? make_float2(acc[mi][ni][2], acc[mi][ni][3])
                                    : make_float2(acc[mi][ni][0], acc[mi][ni][1]);
                    *reinterpret_cast<float2*>(dst + ni * 8) = o;
                }
            }
        }
    }
}

// ---------------- host side ----------------
extern "C" void kernel_launch(void* const* d_in, const int* in_sizes, int n_in,
                              void* d_out, int out_size) {
    (void)in_sizes; (void)n_in; (void)out_size;

    const int*   q_rel     = (const int*)  d_in[1];
    const int*   q_tau     = (const int*)  d_in[2];
    const float* hidden    = (const float*)d_in[3];
    const int*   edges     = (const int*)  d_in[4];
    const float* rela      = (const float*)d_in[7];
    const float* Ws        = (const float*)d_in[8];
    const float* Wr        = (const float*)d_in[9];
    const float* Wqr       = (const float*)d_in[10];
    const float* Wqr_b     = (const float*)d_in[11];
    const float* Wtau      = (const float*)d_in[12];
    const float* w_alpha   = (const float*)d_in[13];
    const float* w_alpha_b = (const float*)d_in[14];
    const float* W_h       = (const float*)d_in[15];
    const float* W_h_s     = (const float*)d_in[16];
    const float* w_t1      = (const float*)d_in[17];
    const float* b_t1      = (const float*)d_in[18];
    const float* w_t2      = (const float*)d_in[19];
    const float* b_t2      = (const float*)d_in[20];
    float* out = (float*)d_out;

    void *p_hsW, *p_agg, *p_agg_s;
    void *p_WhH, *p_WhL, *p_WhsH, *p_WhsL, *p_WsH, *p_WsL;
    cudaGetSymbolAddress(&p_hsW,   d_hsW);
    cudaGetSymbolAddress(&p_agg,   d_agg);
    cudaGetSymbolAddress(&p_agg_s, d_agg_s);
    cudaGetSymbolAddress(&p_WhH,  d_Wh_hi);
    cudaGetSymbolAddress(&p_WhL,  d_Wh_lo);
    cudaGetSymbolAddress(&p_WhsH, d_Whs_hi);
    cudaGetSymbolAddress(&p_WhsL, d_Whs_lo);
    cudaGetSymbolAddress(&p_WsH,  d_Ws_hi);
    cudaGetSymbolAddress(&p_WsL,  d_Ws_lo);

    const int SMEM128 = 34816 + 2 * 128 * 136 * 2;  // 104448
    const int SMEM64  = 34816 + 2 * 128 * 72 * 2;   //  71680
    cudaFuncSetAttribute(mma_gemm<128>, cudaFuncAttributeMaxDynamicSharedMemorySize, SMEM128);
    cudaFuncSetAttribute(mma_gemm<64>,  cudaFuncAttributeMaxDynamicSharedMemorySize, SMEM64);

    // ---- counting sort of edges by obj ----
    hist_zero_kernel<<<(N_NODE + 255) / 256, 256>>>();
    hist_kernel<<<(N_EDGE + 255) / 256, 256>>>(edges);
    scan1_kernel<<<N_SCANB, SCAN_B>>>();
    scan2_kernel<<<1, 32>>>();
    scan3_kernel<<<N_SCANB, SCAN_B>>>();
    fill_kernel<<<(N_EDGE + 255) / 256, 256>>>(edges);

    // ---- small tables + weight images ----
    table_kernel<<<N_RELTAB + N_Q + N_TAU, 128>>>(rela, q_rel, q_tau, Wr, Wqr, Wqr_b,
                                                  Wtau, w_t1, b_t1, w_t2, b_t2);
    wprep_kernel<<<128, 136>>>(W_h, W_h_s, Ws);

    int gm = (N_NODE + 63) / 64;   // 1563
    // ---- hsW = hidden @ Ws ----
    mma_gemm<64><<<gm, 256, SMEM64>>>(hidden, (const __nv_bfloat16*)p_WsH,
                                      (const __nv_bfloat16*)p_WsL, (float*)p_hsW, N_NODE);
    // ---- attention alphas + packed edge records ----
    int nwarp = (N_EDGE + 1) / 2;
    int nblk  = (nwarp * 32 + 255) / 256;
    alpha_kernel<<<nblk, 256>>>(edges, w_alpha, w_alpha_b, q_tau);
    // ---- sorted aggregation: register accumulation, one store per node ----
    agg_kernel<<<(N_NODE * 32 + 255) / 256, 256>>>(hidden, rela);
    // ---- output GEMMs ----
    mma_gemm<128><<<gm, 256, SMEM128>>>((const float*)p_agg,
                                        (const __nv_bfloat16*)p_WhH,
                                        (const __nv_bfloat16*)p_WhL, out, N_NODE);
    mma_gemm<128><<<gm, 256, SMEM128>>>((const float*)p_agg_s,
                                        (const __nv_bfloat16*)p_WhsH,
                                        (const __nv_bfloat16*)p_WhsL,
                                        out + N_NODE * OUT_DIM, N_NODE);
}

// round 7
// speedup vs baseline: 1.3056x; 1.0068x over previous
#include <cuda_runtime.h>
#include <cuda_bf16.h>
#include <math.h>
#include <stdint.h>

#define N_NODE   100000
#define N_EDGE   500000
#define IN_DIM   128
#define OUT_DIM  128
#define ATTN_DIM 64
#define N_RELTAB 401
#define N_Q      64
#define N_TAU    366
#define SCAN_B   1024
#define N_SCANB  ((N_NODE + SCAN_B - 1) / SCAN_B)   // 98

// ---------------- scratch (no allocs allowed) ----------------
__device__ float d_hsW[N_NODE * ATTN_DIM];
__device__ float d_hrW[N_RELTAB * ATTN_DIM];
__device__ float d_qW[N_Q * ATTN_DIM];
__device__ float d_tauW[N_TAU * ATTN_DIM];
__device__ float d_tauTab[N_TAU * IN_DIM];
__device__ float d_agg[N_NODE * IN_DIM];
__device__ float d_agg_s[N_NODE * IN_DIM];

// sort-by-obj machinery
__device__ int d_counts[N_NODE];
__device__ int d_offsets[N_NODE];
__device__ int d_cursor[N_NODE];
__device__ int d_blockSums[N_SCANB + 2];
__device__ int d_pos[N_EDGE];            // sorted position of edge i
__device__ int4 d_edat[N_EDGE];          // sorted {sub, rel, t, alpha_bits}

// pre-converted bf16 hi/lo weight images, padded to SMEM stride
__device__ __nv_bfloat16 d_Wh_hi[128 * 136];
__device__ __nv_bfloat16 d_Wh_lo[128 * 136];
__device__ __nv_bfloat16 d_Whs_hi[128 * 136];
__device__ __nv_bfloat16 d_Whs_lo[128 * 136];
__device__ __nv_bfloat16 d_Ws_hi[128 * 72];
__device__ __nv_bfloat16 d_Ws_lo[128 * 72];

// ---------------- helpers ----------------
__device__ __forceinline__ uint32_t smem_u32(const void* p) {
    uint32_t a;
    asm("{ .reg .u64 t; cvta.to.shared.u64 t, %1; cvt.u32.u64 %0, t; }" : "=r"(a) : "l"(p));
    return a;
}

#define LDSM_X4(r0, r1, r2, r3, addr) \
    asm volatile("ldmatrix.sync.aligned.m8n8.x4.shared.b16 {%0,%1,%2,%3}, [%4];" \
                 : "=r"(r0), "=r"(r1), "=r"(r2), "=r"(r3) : "r"(addr))
#define LDSM_X2T(r0, r1, addr) \
    asm volatile("ldmatrix.sync.aligned.m8n8.x2.trans.shared.b16 {%0,%1}, [%2];" \
                 : "=r"(r0), "=r"(r1) : "r"(addr))
#define MMA16816(c, a0, a1, a2, a3, b0, b1) \
    asm volatile("mma.sync.aligned.m16n8k16.row.col.f32.bf16.bf16.f32 " \
                 "{%0,%1,%2,%3}, {%4,%5,%6,%7}, {%8,%9}, {%0,%1,%2,%3};" \
                 : "+f"((c)[0]), "+f"((c)[1]), "+f"((c)[2]), "+f"((c)[3]) \
                 : "r"(a0), "r"(a1), "r"(a2), "r"(a3), "r"(b0), "r"(b1))

// ---------------- build the small tables ----------------
__global__ void table_kernel(const float* __restrict__ rela,
                             const int*   __restrict__ q_rel,
                             const int*   __restrict__ q_tau_p,
                             const float* __restrict__ Wr,
                             const float* __restrict__ Wqr,
                             const float* __restrict__ Wqr_b,
                             const float* __restrict__ Wtau,
                             const float* __restrict__ w_t1,
                             const float* __restrict__ b_t1,
                             const float* __restrict__ w_t2,
                             const float* __restrict__ b_t2) {
    __shared__ float s[IN_DIM];
    int b   = blockIdx.x;
    int tid = threadIdx.x;

    const float* W = nullptr;
    float* outrow  = nullptr;
    bool  add_bias = false;

    if (b < N_RELTAB) {
        s[tid] = rela[(size_t)b * IN_DIM + tid];
        W = Wr; outrow = d_hrW + b * ATTN_DIM;
    } else if (b < N_RELTAB + N_Q) {
        int r = b - N_RELTAB;
        s[tid] = rela[(size_t)q_rel[r] * IN_DIM + tid];
        W = Wqr; outrow = d_qW + r * ATTN_DIM; add_bias = true;
    } else {
        int t = b - N_RELTAB - N_Q;
        float delta = (float)(t - *q_tau_p);
        float v = w_t1[tid] * delta + b_t1[tid] + sinf(w_t2[tid] * delta + b_t2[tid]);
        s[tid] = v;
        d_tauTab[(size_t)t * IN_DIM + tid] = v;
        W = Wtau; outrow = d_tauW + t * ATTN_DIM;
    }
    __syncthreads();

    if (tid < ATTN_DIM) {
        float acc = add_bias ? Wqr_b[tid] : 0.f;
        #pragma unroll 8
        for (int k = 0; k < IN_DIM; k++)
            acc = fmaf(s[k], W[k * ATTN_DIM + tid], acc);
        outrow[tid] = acc;
    }
}

// ---------------- weight prep ----------------
__global__ void wprep_kernel(const float* __restrict__ Wh,
                             const float* __restrict__ Whs,
                             const float* __restrict__ Ws) {
    int k = blockIdx.x;
    int t = threadIdx.x;

    float w1 = (t < 128) ? Wh[k * 128 + t]  : 0.f;
    __nv_bfloat16 h1 = __float2bfloat16(w1);
    d_Wh_hi[k * 136 + t] = h1;
    d_Wh_lo[k * 136 + t] = __float2bfloat16(w1 - __bfloat162float(h1));

    float w2 = (t < 128) ? Whs[k * 128 + t] : 0.f;
    __nv_bfloat16 h2 = __float2bfloat16(w2);
    d_Whs_hi[k * 136 + t] = h2;
    d_Whs_lo[k * 136 + t] = __float2bfloat16(w2 - __bfloat162float(h2));

    if (t < 72) {
        float w3 = (t < 64) ? Ws[k * 64 + t] : 0.f;
        __nv_bfloat16 h3 = __float2bfloat16(w3);
        d_Ws_hi[k * 72 + t] = h3;
        d_Ws_lo[k * 72 + t] = __float2bfloat16(w3 - __bfloat162float(h3));
    }
}

// ---------------- counting sort of edges by obj ----------------
__global__ void hist_kernel(const int* __restrict__ edges) {
    int i = blockIdx.x * blockDim.x + threadIdx.x;
    if (i < N_EDGE) atomicAdd(&d_counts[edges[(size_t)i * 7 + 6]], 1);
}
__global__ void scan1_kernel() {
    __shared__ int sh[SCAN_B];
    int gid = blockIdx.x * SCAN_B + threadIdx.x;
    int v = (gid < N_NODE) ? d_counts[gid] : 0;
    sh[threadIdx.x] = v;
    __syncthreads();
    #pragma unroll
    for (int off = 1; off < SCAN_B; off <<= 1) {
        int t = (threadIdx.x >= off) ? sh[threadIdx.x - off] : 0;
        __syncthreads();
        sh[threadIdx.x] += t;
        __syncthreads();
    }
    if (gid < N_NODE) d_offsets[gid] = sh[threadIdx.x] - v;   // exclusive
    if (threadIdx.x == SCAN_B - 1) d_blockSums[blockIdx.x] = sh[SCAN_B - 1];
}
// parallel exclusive scan of 98 block sums with one 128-thread block
__global__ void scan2_kernel() {
    __shared__ int warpSum[4];
    int tid = threadIdx.x;                 // 128 threads
    int v = (tid < N_SCANB) ? d_blockSums[tid] : 0;
    int x = v;
    #pragma unroll
    for (int o = 1; o < 32; o <<= 1) {
        int t = __shfl_up_sync(0xffffffffu, x, o);
        if ((tid & 31) >= o) x += t;
    }
    if ((tid & 31) == 31) warpSum[tid >> 5] = x;
    __syncthreads();
    if (tid < 4) {
        int s = warpSum[tid];
        #pragma unroll
        for (int o = 1; o < 4; o <<= 1) {
            int t = __shfl_up_sync(0xfu, s, o);
            if (tid >= o) s += t;
        }
        warpSum[tid] = s - warpSum[tid];   // exclusive warp prefix
    }
    __syncthreads();
    if (tid < N_SCANB) d_blockSums[tid] = x - v + warpSum[tid >> 5];
}
__global__ void scan3_kernel() {
    int gid = blockIdx.x * SCAN_B + threadIdx.x;
    if (gid < N_NODE) {
        int o = d_offsets[gid] + d_blockSums[gid / SCAN_B];
        d_offsets[gid] = o;
        d_cursor[gid]  = o;
    }
}
__global__ void fill_kernel(const int* __restrict__ edges) {
    int i = blockIdx.x * blockDim.x + threadIdx.x;
    if (i < N_EDGE) {
        int obj = edges[(size_t)i * 7 + 6];
        d_pos[i] = atomicAdd(&d_cursor[obj], 1);
    }
}

// ---------------- alpha kernel: writes record to SORTED slot ------------
__global__ void alpha_kernel(const int*   __restrict__ edges,
                             const float* __restrict__ w_alpha,
                             const float* __restrict__ w_alpha_b,
                             const int*   __restrict__ q_tau_p) {
    int pw   = (blockIdx.x * blockDim.x + threadIdx.x) >> 5;
    int lane = threadIdx.x & 31;
    int eid  = pw * 2 + (lane >> 4);
    if (eid >= N_EDGE) return;
    int l = lane & 15;

    const int* e = edges + (size_t)eid * 7;
    int r_idx = e[0];
    int rel   = e[2];
    int tau   = e[4];
    int sub   = e[5];
    int t = (tau >= 0) ? tau : *q_tau_p;

    float4 hv = *reinterpret_cast<const float4*>(d_hsW + (size_t)sub * ATTN_DIM + l * 4);
    float4 rv = *reinterpret_cast<const float4*>(d_hrW + rel   * ATTN_DIM + l * 4);
    float4 qv = *reinterpret_cast<const float4*>(d_qW  + r_idx * ATTN_DIM + l * 4);
    float4 tv = *reinterpret_cast<const float4*>(d_tauW + t    * ATTN_DIM + l * 4);
    float4 wa = *reinterpret_cast<const float4*>(w_alpha + l * 4);

    float s = fmaxf(hv.x + rv.x + qv.x + tv.x, 0.f) * wa.x
            + fmaxf(hv.y + rv.y + qv.y + tv.y, 0.f) * wa.y
            + fmaxf(hv.z + rv.z + qv.z + tv.z, 0.f) * wa.z
            + fmaxf(hv.w + rv.w + qv.w + tv.w, 0.f) * wa.w;
    #pragma unroll
    for (int o = 8; o; o >>= 1) s += __shfl_xor_sync(0xffffffffu, s, o);
    if (l == 0) {
        float al = 1.f / (1.f + expf(-(s + w_alpha_b[0])));
        d_edat[d_pos[eid]] = make_int4(sub, rel, t, __float_as_int(al));
    }
}

// ---------------- aggregation: one warp per node, sequential edat --------
__global__ void __launch_bounds__(256)
agg_kernel(const float* __restrict__ hidden,
           const float* __restrict__ rela) {
    int node = (blockIdx.x * blockDim.x + threadIdx.x) >> 5;
    int lane = threadIdx.x & 31;
    if (node >= N_NODE) return;

    int start = d_offsets[node];
    int cnt   = d_counts[node];

    float4 a1 = make_float4(0.f, 0.f, 0.f, 0.f);
    float4 a2 = make_float4(0.f, 0.f, 0.f, 0.f);

    for (int i = 0; i < cnt; i++) {
        int4 ed = __ldg(&d_edat[start + i]);
        float a = __int_as_float(ed.w);

        float4 hs = *reinterpret_cast<const float4*>(hidden + (size_t)ed.x * IN_DIM + lane * 4);
        float4 hr = *reinterpret_cast<const float4*>(rela   + (size_t)ed.y * IN_DIM + lane * 4);
        float4 ht = *reinterpret_cast<const float4*>(d_tauTab + (size_t)ed.z * IN_DIM + lane * 4);

        float mx = hs.x + hr.x + ht.x;
        float my = hs.y + hr.y + ht.y;
        float mz = hs.z + hr.z + ht.z;
        float mw = hs.w + hr.w + ht.w;
        a1.x = fmaf(a, mx, a1.x); a1.y = fmaf(a, my, a1.y);
        a1.z = fmaf(a, mz, a1.z); a1.w = fmaf(a, mw, a1.w);
        a2.x += mx - a * mx; a2.y += my - a * my;
        a2.z += mz - a * mz; a2.w += mw - a * mw;
    }

    *reinterpret_cast<float4*>(d_agg   + (size_t)node * IN_DIM + lane * 4) = a1;
    *reinterpret_cast<float4*>(d_agg_s + (size_t)node * IN_DIM + lane * 4) = a2;
}

// ---------------- tensor-core GEMM via mma.sync, BM = 64, merged loop ----
// blockIdx.y selects (A, B, C) set when pairs != null
template<int N>
__global__ void __launch_bounds__(256)
mma_gemm(const float* __restrict__ A0, const float* __restrict__ A1,
         const __nv_bfloat16* __restrict__ imgBh0, const __nv_bfloat16* __restrict__ imgBl0,
         const __nv_bfloat16* __restrict__ imgBh1, const __nv_bfloat16* __restrict__ imgBl1,
         float* __restrict__ C0, float* __restrict__ C1, int M) {
    constexpr int K      = 128;
    constexpr int BM     = 64;
    constexpr int SA_STR = K + 8;
    constexpr int SB_STR = N + 8;
    constexpr int OFF_AH = 0;
    constexpr int OFF_AL = OFF_AH + BM * SA_STR * 2;
    constexpr int OFF_BH = OFF_AL + BM * SA_STR * 2;
    constexpr int OFF_BL = OFF_BH + K * SB_STR * 2;
    constexpr int WN     = N / 4;
    constexpr int NF     = WN / 8;
    constexpr int BCNT   = K * SB_STR * 2 / 16;

    extern __shared__ __align__(16) char smem[];
    const uint32_t sbase = smem_u32(smem);

    const int tid  = threadIdx.x;
    const int wid  = tid >> 5;
    const int lane = tid & 31;
    const int wm   = wid >> 2;
    const int wn   = wid & 3;
    const int row0 = blockIdx.x * BM;

    const float* A = blockIdx.y ? A1 : A0;
    const __nv_bfloat16* imgBh = blockIdx.y ? imgBh1 : imgBh0;
    const __nv_bfloat16* imgBl = blockIdx.y ? imgBl1 : imgBl0;
    float* C = blockIdx.y ? C1 : C0;

    {
        const int4* sh = reinterpret_cast<const int4*>(imgBh);
        const int4* sl = reinterpret_cast<const int4*>(imgBl);
        int4* dh = reinterpret_cast<int4*>(smem + OFF_BH);
        int4* dl = reinterpret_cast<int4*>(smem + OFF_BL);
        #pragma unroll
        for (int i = tid; i < BCNT; i += 256) { dh[i] = sh[i]; dl[i] = sl[i]; }
    }

    {
        int row = tid >> 2;
        int q   = tid & 3;
        int grow = row0 + row;
        bool valid = grow < M;
        const float4* src = reinterpret_cast<const float4*>(A + (size_t)grow * K + q * 32);
        #pragma unroll
        for (int j = 0; j < 8; j++) {
            float4 v = valid ? src[j] : make_float4(0.f, 0.f, 0.f, 0.f);
            uint32_t h01, h23, l01, l23;
            asm("cvt.rn.bf16x2.f32 %0, %1, %2;" : "=r"(h01) : "f"(v.y), "f"(v.x));
            asm("cvt.rn.bf16x2.f32 %0, %1, %2;" : "=r"(h23) : "f"(v.w), "f"(v.z));
            float r0 = v.x - __uint_as_float(h01 << 16);
            float r1 = v.y - __uint_as_float(h01 & 0xffff0000u);
            float r2 = v.z - __uint_as_float(h23 << 16);
            float r3 = v.w - __uint_as_float(h23 & 0xffff0000u);
            asm("cvt.rn.bf16x2.f32 %0, %1, %2;" : "=r"(l01) : "f"(r1), "f"(r0));
            asm("cvt.rn.bf16x2.f32 %0, %1, %2;" : "=r"(l23) : "f"(r3), "f"(r2));
            int col = q * 32 + j * 4;
            uint32_t o = (uint32_t)(row * SA_STR + col) * 2;
            *reinterpret_cast<uint32_t*>(smem + OFF_AH + o)     = h01;
            *reinterpret_cast<uint32_t*>(smem + OFF_AH + o + 4) = h23;
            *reinterpret_cast<uint32_t*>(smem + OFF_AL + o)     = l01;
            *reinterpret_cast<uint32_t*>(smem + OFF_AL + o + 4) = l23;
        }
    }
    __syncthreads();

    float acc[2][NF][4];
    #pragma unroll
    for (int mi = 0; mi < 2; mi++)
        #pragma unroll
        for (int ni = 0; ni < NF; ni++)
            #pragma unroll
            for (int j = 0; j < 4; j++) acc[mi][ni][j] = 0.f;

    const int lrow = lane & 15;
    const int lcol = (lane >> 4) * 8;
    const uint32_t b_col = (uint32_t)(wn * WN) * 2;

    #pragma unroll
    for (int kk = 0; kk < 8; kk++) {
        uint32_t bh[NF][2], bl[NF][2];
        #pragma unroll
        for (int ni = 0; ni < NF; ni++) {
            uint32_t rowoff = (uint32_t)(kk * 16 + lrow) * (SB_STR * 2)
                            + b_col + (uint32_t)ni * 16;
            LDSM_X2T(bh[ni][0], bh[ni][1], sbase + OFF_BH + rowoff);
            LDSM_X2T(bl[ni][0], bl[ni][1], sbase + OFF_BL + rowoff);
        }
        #pragma unroll
        for (int mi = 0; mi < 2; mi++) {
            uint32_t arow = (uint32_t)(wm * 32 + mi * 16 + lrow) * (SA_STR * 2)
                          + (uint32_t)(kk * 16 + lcol) * 2;
            uint32_t ah0, ah1, ah2, ah3, al0, al1, al2, al3;
            LDSM_X4(ah0, ah1, ah2, ah3, sbase + OFF_AH + arow);
            LDSM_X4(al0, al1, al2, al3, sbase + OFF_AL + arow);
            #pragma unroll
            for (int ni = 0; ni < NF; ni++) {
                MMA16816(acc[mi][ni], ah0, ah1, ah2, ah3, bh[ni][0], bh[ni][1]);
                MMA16816(acc[mi][ni], al0, al1, al2, al3, bh[ni][0], bh[ni][1]);
                MMA16816(acc[mi][ni], ah0, ah1, ah2, ah3, bl[ni][0], bl[ni][1]);
            }
        }
    }

    const int g = lane >> 2;
    const int t = lane & 3;
    #pragma unroll
    for (int mi = 0; mi < 2; mi++) {
        int r_hi = row0 + wm * 32 + mi * 16 + g;
        #pragma unroll
        for (int half = 0; half < 2; half++) {
            int r = r_hi + half * 8;
            if (r < M) {
                float* dst = C + (size_t)r * N + wn * WN + t * 2;
                #pragma unroll
                for (int ni = 0; ni < NF; ni++) {
                    float2 o = half ? make_float2(acc[mi][ni][2], acc[mi][ni][3])
                                    : make_float2(acc[mi][ni][0], acc[mi][ni][1]);
                    *reinterpret_cast<float2*>(dst + ni * 8) = o;
                }
            }
        }
    }
}

// ---------------- host side ----------------
extern "C" void kernel_launch(void* const* d_in, const int* in_sizes, int n_in,
                              void* d_out, int out_size) {
    (void)in_sizes; (void)n_in; (void)out_size;

    const int*   q_rel     = (const int*)  d_in[1];
    const int*   q_tau     = (const int*)  d_in[2];
    const float* hidden    = (const float*)d_in[3];
    const int*   edges     = (const int*)  d_in[4];
    const float* rela      = (const float*)d_in[7];
    const float* Ws        = (const float*)d_in[8];
    const float* Wr        = (const float*)d_in[9];
    const float* Wqr       = (const float*)d_in[10];
    const float* Wqr_b     = (const float*)d_in[11];
    const float* Wtau      = (const float*)d_in[12];
    const float* w_alpha   = (const float*)d_in[13];
    const float* w_alpha_b = (const float*)d_in[14];
    const float* W_h       = (const float*)d_in[15];
    const float* W_h_s     = (const float*)d_in[16];
    const float* w_t1      = (const float*)d_in[17];
    const float* b_t1      = (const float*)d_in[18];
    const float* w_t2      = (const float*)d_in[19];
    const float* b_t2      = (const float*)d_in[20];
    float* out = (float*)d_out;

    void *p_hsW, *p_agg, *p_agg_s, *p_counts;
    void *p_WhH, *p_WhL, *p_WhsH, *p_WhsL, *p_WsH, *p_WsL;
    cudaGetSymbolAddress(&p_hsW,    d_hsW);
    cudaGetSymbolAddress(&p_agg,    d_agg);
    cudaGetSymbolAddress(&p_agg_s,  d_agg_s);
    cudaGetSymbolAddress(&p_counts, d_counts);
    cudaGetSymbolAddress(&p_WhH,  d_Wh_hi);
    cudaGetSymbolAddress(&p_WhL,  d_Wh_lo);
    cudaGetSymbolAddress(&p_WhsH, d_Whs_hi);
    cudaGetSymbolAddress(&p_WhsL, d_Whs_lo);
    cudaGetSymbolAddress(&p_WsH,  d_Ws_hi);
    cudaGetSymbolAddress(&p_WsL,  d_Ws_lo);

    const int SMEM128 = 34816 + 2 * 128 * 136 * 2;  // 104448
    const int SMEM64  = 34816 + 2 * 128 * 72 * 2;   //  71680
    cudaFuncSetAttribute(mma_gemm<128>, cudaFuncAttributeMaxDynamicSharedMemorySize, SMEM128);
    cudaFuncSetAttribute(mma_gemm<64>,  cudaFuncAttributeMaxDynamicSharedMemorySize, SMEM64);

    // ---- counting sort of edges by obj ----
    cudaMemsetAsync(p_counts, 0, N_NODE * sizeof(int));
    hist_kernel<<<(N_EDGE + 255) / 256, 256>>>(edges);
    scan1_kernel<<<N_SCANB, SCAN_B>>>();
    scan2_kernel<<<1, 128>>>();
    scan3_kernel<<<N_SCANB, SCAN_B>>>();
    fill_kernel<<<(N_EDGE + 255) / 256, 256>>>(edges);

    // ---- small tables + weight images ----
    table_kernel<<<N_RELTAB + N_Q + N_TAU, 128>>>(rela, q_rel, q_tau, Wr, Wqr, Wqr_b,
                                                  Wtau, w_t1, b_t1, w_t2, b_t2);
    wprep_kernel<<<128, 136>>>(W_h, W_h_s, Ws);

    int gm = (N_NODE + 63) / 64;   // 1563
    // ---- hsW = hidden @ Ws ----
    mma_gemm<64><<<dim3(gm, 1), 256, SMEM64>>>(
        hidden, nullptr,
        (const __nv_bfloat16*)p_WsH, (const __nv_bfloat16*)p_WsL,
        nullptr, nullptr,
        (float*)p_hsW, nullptr, N_NODE);
    // ---- attention alphas -> sorted records ----
    int nwarp = (N_EDGE + 1) / 2;
    int nblk  = (nwarp * 32 + 255) / 256;
    alpha_kernel<<<nblk, 256>>>(edges, w_alpha, w_alpha_b, q_tau);
    // ---- sorted aggregation ----
    agg_kernel<<<(N_NODE * 32 + 255) / 256, 256>>>(hidden, rela);
    // ---- output GEMMs (one launch, blockIdx.y selects pair) ----
    mma_gemm<128><<<dim3(gm, 2), 256, SMEM128>>>(
        (const float*)p_agg, (const float*)p_agg_s,
        (const __nv_bfloat16*)p_WhH, (const __nv_bfloat16*)p_WhL,
        (const __nv_bfloat16*)p_WhsH, (const __nv_bfloat16*)p_WhsL,
        out, out + N_NODE * OUT_DIM, N_NODE);
}

// round 8
// speedup vs baseline: 1.3600x; 1.0417x over previous
#include <cuda_runtime.h>
#include <cuda_bf16.h>
#include <math.h>
#include <stdint.h>

#define N_NODE   100000
#define N_EDGE   500000
#define IN_DIM   128
#define OUT_DIM  128
#define ATTN_DIM 64
#define N_RELTAB 401
#define N_Q      64
#define N_TAU    366
#define SCAN_B   1024
#define N_SCANB  ((N_NODE + SCAN_B - 1) / SCAN_B)   // 98

// ---------------- scratch (no allocs allowed) ----------------
__device__ float d_hsW[N_NODE * ATTN_DIM];
__device__ float d_hrW[N_RELTAB * ATTN_DIM];
__device__ float d_qW[N_Q * ATTN_DIM];
__device__ float d_tauW[N_TAU * ATTN_DIM];
__device__ float d_tauTab[N_TAU * IN_DIM];
__device__ float d_agg[N_NODE * IN_DIM];
__device__ float d_agg_s[N_NODE * IN_DIM];

// sort-by-obj machinery
__device__ int d_counts[N_NODE];
__device__ int d_offsets[N_NODE];
__device__ int d_cursor[N_NODE];
__device__ int d_blockSums[N_SCANB + 2];
__device__ int d_pos[N_EDGE];
__device__ int4 d_edat[N_EDGE];          // sorted {sub, rel, t, alpha_bits}

// pre-converted bf16 hi/lo weight images, padded to SMEM stride
__device__ __nv_bfloat16 d_Wh_hi[128 * 136];
__device__ __nv_bfloat16 d_Wh_lo[128 * 136];
__device__ __nv_bfloat16 d_Whs_hi[128 * 136];
__device__ __nv_bfloat16 d_Whs_lo[128 * 136];
__device__ __nv_bfloat16 d_Ws_hi[128 * 72];
__device__ __nv_bfloat16 d_Ws_lo[128 * 72];

// ---------------- helpers ----------------
__device__ __forceinline__ uint32_t smem_u32(const void* p) {
    uint32_t a;
    asm("{ .reg .u64 t; cvta.to.shared.u64 t, %1; cvt.u32.u64 %0, t; }" : "=r"(a) : "l"(p));
    return a;
}

#define LDSM_X4(r0, r1, r2, r3, addr) \
    asm volatile("ldmatrix.sync.aligned.m8n8.x4.shared.b16 {%0,%1,%2,%3}, [%4];" \
                 : "=r"(r0), "=r"(r1), "=r"(r2), "=r"(r3) : "r"(addr))
#define LDSM_X2T(r0, r1, addr) \
    asm volatile("ldmatrix.sync.aligned.m8n8.x2.trans.shared.b16 {%0,%1}, [%2];" \
                 : "=r"(r0), "=r"(r1) : "r"(addr))
#define MMA16816(c, a0, a1, a2, a3, b0, b1) \
    asm volatile("mma.sync.aligned.m16n8k16.row.col.f32.bf16.bf16.f32 " \
                 "{%0,%1,%2,%3}, {%4,%5,%6,%7}, {%8,%9}, {%0,%1,%2,%3};" \
                 : "+f"((c)[0]), "+f"((c)[1]), "+f"((c)[2]), "+f"((c)[3]) \
                 : "r"(a0), "r"(a1), "r"(a2), "r"(a3), "r"(b0), "r"(b1))

// ---------------- build the small tables ----------------
__global__ void table_kernel(const float* __restrict__ rela,
                             const int*   __restrict__ q_rel,
                             const int*   __restrict__ q_tau_p,
                             const float* __restrict__ Wr,
                             const float* __restrict__ Wqr,
                             const float* __restrict__ Wqr_b,
                             const float* __restrict__ Wtau,
                             const float* __restrict__ w_t1,
                             const float* __restrict__ b_t1,
                             const float* __restrict__ w_t2,
                             const float* __restrict__ b_t2) {
    __shared__ float s[IN_DIM];
    int b   = blockIdx.x;
    int tid = threadIdx.x;

    const float* W = nullptr;
    float* outrow  = nullptr;
    bool  add_bias = false;

    if (b < N_RELTAB) {
        s[tid] = rela[(size_t)b * IN_DIM + tid];
        W = Wr; outrow = d_hrW + b * ATTN_DIM;
    } else if (b < N_RELTAB + N_Q) {
        int r = b - N_RELTAB;
        s[tid] = rela[(size_t)q_rel[r] * IN_DIM + tid];
        W = Wqr; outrow = d_qW + r * ATTN_DIM; add_bias = true;
    } else {
        int t = b - N_RELTAB - N_Q;
        float delta = (float)(t - *q_tau_p);
        float v = w_t1[tid] * delta + b_t1[tid] + sinf(w_t2[tid] * delta + b_t2[tid]);
        s[tid] = v;
        d_tauTab[(size_t)t * IN_DIM + tid] = v;
        W = Wtau; outrow = d_tauW + t * ATTN_DIM;
    }
    __syncthreads();

    if (tid < ATTN_DIM) {
        float acc = add_bias ? Wqr_b[tid] : 0.f;
        #pragma unroll 8
        for (int k = 0; k < IN_DIM; k++)
            acc = fmaf(s[k], W[k * ATTN_DIM + tid], acc);
        outrow[tid] = acc;
    }
}

// ---------------- weight prep ----------------
__global__ void wprep_kernel(const float* __restrict__ Wh,
                             const float* __restrict__ Whs,
                             const float* __restrict__ Ws) {
    int k = blockIdx.x;
    int t = threadIdx.x;

    float w1 = (t < 128) ? Wh[k * 128 + t]  : 0.f;
    __nv_bfloat16 h1 = __float2bfloat16(w1);
    d_Wh_hi[k * 136 + t] = h1;
    d_Wh_lo[k * 136 + t] = __float2bfloat16(w1 - __bfloat162float(h1));

    float w2 = (t < 128) ? Whs[k * 128 + t] : 0.f;
    __nv_bfloat16 h2 = __float2bfloat16(w2);
    d_Whs_hi[k * 136 + t] = h2;
    d_Whs_lo[k * 136 + t] = __float2bfloat16(w2 - __bfloat162float(h2));

    if (t < 72) {
        float w3 = (t < 64) ? Ws[k * 64 + t] : 0.f;
        __nv_bfloat16 h3 = __float2bfloat16(w3);
        d_Ws_hi[k * 72 + t] = h3;
        d_Ws_lo[k * 72 + t] = __float2bfloat16(w3 - __bfloat162float(h3));
    }
}

// ---------------- counting sort of edges by obj ----------------
__global__ void hist_kernel(const int* __restrict__ edges) {
    int i = blockIdx.x * blockDim.x + threadIdx.x;
    if (i < N_EDGE) atomicAdd(&d_counts[edges[(size_t)i * 7 + 6]], 1);
}
__global__ void scan1_kernel() {
    __shared__ int sh[SCAN_B];
    int gid = blockIdx.x * SCAN_B + threadIdx.x;
    int v = (gid < N_NODE) ? d_counts[gid] : 0;
    sh[threadIdx.x] = v;
    __syncthreads();
    #pragma unroll
    for (int off = 1; off < SCAN_B; off <<= 1) {
        int t = (threadIdx.x >= off) ? sh[threadIdx.x - off] : 0;
        __syncthreads();
        sh[threadIdx.x] += t;
        __syncthreads();
    }
    if (gid < N_NODE) d_offsets[gid] = sh[threadIdx.x] - v;
    if (threadIdx.x == SCAN_B - 1) d_blockSums[blockIdx.x] = sh[SCAN_B - 1];
}
__global__ void scan2_kernel() {
    __shared__ int warpSum[4];
    int tid = threadIdx.x;                 // 128 threads
    int v = (tid < N_SCANB) ? d_blockSums[tid] : 0;
    int x = v;
    #pragma unroll
    for (int o = 1; o < 32; o <<= 1) {
        int t = __shfl_up_sync(0xffffffffu, x, o);
        if ((tid & 31) >= o) x += t;
    }
    if ((tid & 31) == 31) warpSum[tid >> 5] = x;
    __syncthreads();
    if (tid < 4) {
        int s = warpSum[tid];
        #pragma unroll
        for (int o = 1; o < 4; o <<= 1) {
            int t = __shfl_up_sync(0xfu, s, o);
            if (tid >= o) s += t;
        }
        warpSum[tid] = s - warpSum[tid];
    }
    __syncthreads();
    if (tid < N_SCANB) d_blockSums[tid] = x - v + warpSum[tid >> 5];
}
__global__ void scan3_kernel() {
    int gid = blockIdx.x * SCAN_B + threadIdx.x;
    if (gid < N_NODE) {
        int o = d_offsets[gid] + d_blockSums[gid / SCAN_B];
        d_offsets[gid] = o;
        d_cursor[gid]  = o;
    }
}
__global__ void fill_kernel(const int* __restrict__ edges) {
    int i = blockIdx.x * blockDim.x + threadIdx.x;
    if (i < N_EDGE) {
        int obj = edges[(size_t)i * 7 + 6];
        d_pos[i] = atomicAdd(&d_cursor[obj], 1);
    }
}

// ---------------- alpha kernel: writes record to SORTED slot ------------
__global__ void alpha_kernel(const int*   __restrict__ edges,
                             const float* __restrict__ w_alpha,
                             const float* __restrict__ w_alpha_b,
                             const int*   __restrict__ q_tau_p) {
    int pw   = (blockIdx.x * blockDim.x + threadIdx.x) >> 5;
    int lane = threadIdx.x & 31;
    int eid  = pw * 2 + (lane >> 4);
    if (eid >= N_EDGE) return;
    int l = lane & 15;

    const int* e = edges + (size_t)eid * 7;
    int r_idx = e[0];
    int rel   = e[2];
    int tau   = e[4];
    int sub   = e[5];
    int t = (tau >= 0) ? tau : *q_tau_p;

    float4 hv = *reinterpret_cast<const float4*>(d_hsW + (size_t)sub * ATTN_DIM + l * 4);
    float4 rv = *reinterpret_cast<const float4*>(d_hrW + rel   * ATTN_DIM + l * 4);
    float4 qv = *reinterpret_cast<const float4*>(d_qW  + r_idx * ATTN_DIM + l * 4);
    float4 tv = *reinterpret_cast<const float4*>(d_tauW + t    * ATTN_DIM + l * 4);
    float4 wa = *reinterpret_cast<const float4*>(w_alpha + l * 4);

    float s = fmaxf(hv.x + rv.x + qv.x + tv.x, 0.f) * wa.x
            + fmaxf(hv.y + rv.y + qv.y + tv.y, 0.f) * wa.y
            + fmaxf(hv.z + rv.z + qv.z + tv.z, 0.f) * wa.z
            + fmaxf(hv.w + rv.w + qv.w + tv.w, 0.f) * wa.w;
    #pragma unroll
    for (int o = 8; o; o >>= 1) s += __shfl_xor_sync(0xffffffffu, s, o);
    if (l == 0) {
        float al = 1.f / (1.f + expf(-(s + w_alpha_b[0])));
        d_edat[d_pos[eid]] = make_int4(sub, rel, t, __float_as_int(al));
    }
}

// ---------------- aggregation: one warp per node, 2-way unrolled ---------
__global__ void __launch_bounds__(256)
agg_kernel(const float* __restrict__ hidden,
           const float* __restrict__ rela) {
    int node = (blockIdx.x * blockDim.x + threadIdx.x) >> 5;
    int lane = threadIdx.x & 31;
    if (node >= N_NODE) return;

    int start = d_offsets[node];
    int cnt   = d_counts[node];

    float4 a1 = make_float4(0.f, 0.f, 0.f, 0.f);
    float4 a2 = make_float4(0.f, 0.f, 0.f, 0.f);

    int i = 0;
    for (; i + 2 <= cnt; i += 2) {
        int4 e0 = __ldg(&d_edat[start + i]);
        int4 e1 = __ldg(&d_edat[start + i + 1]);
        float av0 = __int_as_float(e0.w);
        float av1 = __int_as_float(e1.w);

        float4 hs0 = *reinterpret_cast<const float4*>(hidden + (size_t)e0.x * IN_DIM + lane * 4);
        float4 hs1 = *reinterpret_cast<const float4*>(hidden + (size_t)e1.x * IN_DIM + lane * 4);
        float4 hr0 = *reinterpret_cast<const float4*>(rela   + (size_t)e0.y * IN_DIM + lane * 4);
        float4 hr1 = *reinterpret_cast<const float4*>(rela   + (size_t)e1.y * IN_DIM + lane * 4);
        float4 ht0 = *reinterpret_cast<const float4*>(d_tauTab + (size_t)e0.z * IN_DIM + lane * 4);
        float4 ht1 = *reinterpret_cast<const float4*>(d_tauTab + (size_t)e1.z * IN_DIM + lane * 4);

        float mx0 = hs0.x + hr0.x + ht0.x, my0 = hs0.y + hr0.y + ht0.y;
        float mz0 = hs0.z + hr0.z + ht0.z, mw0 = hs0.w + hr0.w + ht0.w;
        float mx1 = hs1.x + hr1.x + ht1.x, my1 = hs1.y + hr1.y + ht1.y;
        float mz1 = hs1.z + hr1.z + ht1.z, mw1 = hs1.w + hr1.w + ht1.w;

        a1.x = fmaf(av0, mx0, fmaf(av1, mx1, a1.x));
        a1.y = fmaf(av0, my0, fmaf(av1, my1, a1.y));
        a1.z = fmaf(av0, mz0, fmaf(av1, mz1, a1.z));
        a1.w = fmaf(av0, mw0, fmaf(av1, mw1, a1.w));
        a2.x += (mx0 - av0 * mx0) + (mx1 - av1 * mx1);
        a2.y += (my0 - av0 * my0) + (my1 - av1 * my1);
        a2.z += (mz0 - av0 * mz0) + (mz1 - av1 * mz1);
        a2.w += (mw0 - av0 * mw0) + (mw1 - av1 * mw1);
    }
    if (i < cnt) {
        int4 e0 = __ldg(&d_edat[start + i]);
        float av0 = __int_as_float(e0.w);
        float4 hs0 = *reinterpret_cast<const float4*>(hidden + (size_t)e0.x * IN_DIM + lane * 4);
        float4 hr0 = *reinterpret_cast<const float4*>(rela   + (size_t)e0.y * IN_DIM + lane * 4);
        float4 ht0 = *reinterpret_cast<const float4*>(d_tauTab + (size_t)e0.z * IN_DIM + lane * 4);
        float mx0 = hs0.x + hr0.x + ht0.x, my0 = hs0.y + hr0.y + ht0.y;
        float mz0 = hs0.z + hr0.z + ht0.z, mw0 = hs0.w + hr0.w + ht0.w;
        a1.x = fmaf(av0, mx0, a1.x); a1.y = fmaf(av0, my0, a1.y);
        a1.z = fmaf(av0, mz0, a1.z); a1.w = fmaf(av0, mw0, a1.w);
        a2.x += mx0 - av0 * mx0; a2.y += my0 - av0 * my0;
        a2.z += mz0 - av0 * mz0; a2.w += mw0 - av0 * mw0;
    }

    *reinterpret_cast<float4*>(d_agg   + (size_t)node * IN_DIM + lane * 4) = a1;
    *reinterpret_cast<float4*>(d_agg_s + (size_t)node * IN_DIM + lane * 4) = a2;
}

// ---------------- GEMM tile helpers ----------------
// A tile load (64 rows x 128 cols) into registers
__device__ __forceinline__ void load_A_regs(const float* __restrict__ A, int row0,
                                            int tid, int M, float4* v) {
    int row  = tid >> 2;
    int q    = tid & 3;
    int grow = row0 + row;
    bool valid = grow < M;
    const float4* src = reinterpret_cast<const float4*>(A + (size_t)grow * 128 + q * 32);
    #pragma unroll
    for (int j = 0; j < 8; j++)
        v[j] = valid ? src[j] : make_float4(0.f, 0.f, 0.f, 0.f);
}

// split-convert + STS into the A hi/lo buffers
__device__ __forceinline__ void sts_A(char* smem, int offAH, int offAL,
                                      int tid, const float4* v) {
    constexpr int SA_STR = 136;
    int row = tid >> 2;
    int q   = tid & 3;
    #pragma unroll
    for (int j = 0; j < 8; j++) {
        float4 x = v[j];
        uint32_t h01, h23, l01, l23;
        asm("cvt.rn.bf16x2.f32 %0, %1, %2;" : "=r"(h01) : "f"(x.y), "f"(x.x));
        asm("cvt.rn.bf16x2.f32 %0, %1, %2;" : "=r"(h23) : "f"(x.w), "f"(x.z));
        float r0 = x.x - __uint_as_float(h01 << 16);
        float r1 = x.y - __uint_as_float(h01 & 0xffff0000u);
        float r2 = x.z - __uint_as_float(h23 << 16);
        float r3 = x.w - __uint_as_float(h23 & 0xffff0000u);
        asm("cvt.rn.bf16x2.f32 %0, %1, %2;" : "=r"(l01) : "f"(r1), "f"(r0));
        asm("cvt.rn.bf16x2.f32 %0, %1, %2;" : "=r"(l23) : "f"(r3), "f"(r2));
        int col = q * 32 + j * 4;
        uint32_t o = (uint32_t)(row * SA_STR + col) * 2;
        *reinterpret_cast<uint32_t*>(smem + offAH + o)     = h01;
        *reinterpret_cast<uint32_t*>(smem + offAH + o + 4) = h23;
        *reinterpret_cast<uint32_t*>(smem + offAL + o)     = l01;
        *reinterpret_cast<uint32_t*>(smem + offAL + o + 4) = l23;
    }
}

// mainloop + epilogue for one 64-row tile
template<int N>
__device__ __forceinline__ void tile_compute_store(uint32_t sbase, int wm, int wn,
                                                   int lane, int row0, int M,
                                                   float* __restrict__ C) {
    constexpr int SA_STR = 136;
    constexpr int SB_STR = N + 8;
    constexpr int OFF_AH = 0;
    constexpr int OFF_AL = OFF_AH + 64 * SA_STR * 2;
    constexpr int OFF_BH = OFF_AL + 64 * SA_STR * 2;
    constexpr int OFF_BL = OFF_BH + 128 * SB_STR * 2;
    constexpr int WN     = N / 4;
    constexpr int NF     = WN / 8;

    float acc[2][NF][4];
    #pragma unroll
    for (int mi = 0; mi < 2; mi++)
        #pragma unroll
        for (int ni = 0; ni < NF; ni++)
            #pragma unroll
            for (int j = 0; j < 4; j++) acc[mi][ni][j] = 0.f;

    const int lrow = lane & 15;
    const int lcol = (lane >> 4) * 8;
    const uint32_t b_col = (uint32_t)(wn * WN) * 2;

    #pragma unroll
    for (int kk = 0; kk < 8; kk++) {
        uint32_t bh[NF][2], bl[NF][2];
        #pragma unroll
        for (int ni = 0; ni < NF; ni++) {
            uint32_t rowoff = (uint32_t)(kk * 16 + lrow) * (SB_STR * 2)
                            + b_col + (uint32_t)ni * 16;
            LDSM_X2T(bh[ni][0], bh[ni][1], sbase + OFF_BH + rowoff);
            LDSM_X2T(bl[ni][0], bl[ni][1], sbase + OFF_BL + rowoff);
        }
        #pragma unroll
        for (int mi = 0; mi < 2; mi++) {
            uint32_t arow = (uint32_t)(wm * 32 + mi * 16 + lrow) * (SA_STR * 2)
                          + (uint32_t)(kk * 16 + lcol) * 2;
            uint32_t ah0, ah1, ah2, ah3, al0, al1, al2, al3;
            LDSM_X4(ah0, ah1, ah2, ah3, sbase + OFF_AH + arow);
            LDSM_X4(al0, al1, al2, al3, sbase + OFF_AL + arow);
            #pragma unroll
            for (int ni = 0; ni < NF; ni++) {
                MMA16816(acc[mi][ni], ah0, ah1, ah2, ah3, bh[ni][0], bh[ni][1]);
                MMA16816(acc[mi][ni], al0, al1, al2, al3, bh[ni][0], bh[ni][1]);
                MMA16816(acc[mi][ni], ah0, ah1, ah2, ah3, bl[ni][0], bl[ni][1]);
            }
        }
    }

    const int g = lane >> 2;
    const int t = lane & 3;
    #pragma unroll
    for (int mi = 0; mi < 2; mi++) {
        int r_hi = row0 + wm * 32 + mi * 16 + g;
        #pragma unroll
        for (int half = 0; half < 2; half++) {
            int r = r_hi + half * 8;
            if (r < M) {
                float* dst = C + (size_t)r * N + wn * WN + t * 2;
                #pragma unroll
                for (int ni = 0; ni < NF; ni++) {
                    float2 o = half ? make_float2(acc[mi][ni][2], acc[mi][ni][3])
                                    : make_float2(acc[mi][ni][0], acc[mi][ni][1]);
                    *reinterpret_cast<float2*>(dst + ni * 8) = o;
                }
            }
        }
    }
}

// ---------------- tensor-core GEMM: 2 tiles (128 rows) per CTA ----------
template<int N>
__global__ void __launch_bounds__(256)
mma_gemm(const float* __restrict__ A0, const float* __restrict__ A1,
         const __nv_bfloat16* __restrict__ imgBh0, const __nv_bfloat16* __restrict__ imgBl0,
         const __nv_bfloat16* __restrict__ imgBh1, const __nv_bfloat16* __restrict__ imgBl1,
         float* __restrict__ C0, float* __restrict__ C1, int M) {
    constexpr int SA_STR = 136;
    constexpr int SB_STR = N + 8;
    constexpr int OFF_AH = 0;
    constexpr int OFF_AL = OFF_AH + 64 * SA_STR * 2;
    constexpr int OFF_BH = OFF_AL + 64 * SA_STR * 2;
    constexpr int OFF_BL = OFF_BH + 128 * SB_STR * 2;
    constexpr int BCNT   = 128 * SB_STR * 2 / 16;

    extern __shared__ __align__(16) char smem[];
    const uint32_t sbase = smem_u32(smem);

    const int tid  = threadIdx.x;
    const int wid  = tid >> 5;
    const int lane = tid & 31;
    const int wm   = wid >> 2;
    const int wn   = wid & 3;
    const int row0 = blockIdx.x * 128;
    const int row1 = row0 + 64;

    const float* A = blockIdx.y ? A1 : A0;
    const __nv_bfloat16* imgBh = blockIdx.y ? imgBh1 : imgBh0;
    const __nv_bfloat16* imgBl = blockIdx.y ? imgBl1 : imgBl0;
    float* C = blockIdx.y ? C1 : C0;

    // B images (once per CTA, L2-hot)
    {
        const int4* sh = reinterpret_cast<const int4*>(imgBh);
        const int4* sl = reinterpret_cast<const int4*>(imgBl);
        int4* dh = reinterpret_cast<int4*>(smem + OFF_BH);
        int4* dl = reinterpret_cast<int4*>(smem + OFF_BL);
        #pragma unroll
        for (int i = tid; i < BCNT; i += 256) { dh[i] = sh[i]; dl[i] = sl[i]; }
    }

    // tile0 A: load + convert + STS
    float4 av[8];
    load_A_regs(A, row0, tid, M, av);
    sts_A(smem, OFF_AH, OFF_AL, tid, av);
    __syncthreads();

    // prefetch tile1 A while tile0 computes
    float4 av1[8];
    load_A_regs(A, row1, tid, M, av1);

    tile_compute_store<N>(sbase, wm, wn, lane, row0, M, C);
    __syncthreads();

    sts_A(smem, OFF_AH, OFF_AL, tid, av1);
    __syncthreads();

    tile_compute_store<N>(sbase, wm, wn, lane, row1, M, C);
}

// ---------------- host side ----------------
extern "C" void kernel_launch(void* const* d_in, const int* in_sizes, int n_in,
                              void* d_out, int out_size) {
    (void)in_sizes; (void)n_in; (void)out_size;

    const int*   q_rel     = (const int*)  d_in[1];
    const int*   q_tau     = (const int*)  d_in[2];
    const float* hidden    = (const float*)d_in[3];
    const int*   edges     = (const int*)  d_in[4];
    const float* rela      = (const float*)d_in[7];
    const float* Ws        = (const float*)d_in[8];
    const float* Wr        = (const float*)d_in[9];
    const float* Wqr       = (const float*)d_in[10];
    const float* Wqr_b     = (const float*)d_in[11];
    const float* Wtau      = (const float*)d_in[12];
    const float* w_alpha   = (const float*)d_in[13];
    const float* w_alpha_b = (const float*)d_in[14];
    const float* W_h       = (const float*)d_in[15];
    const float* W_h_s     = (const float*)d_in[16];
    const float* w_t1      = (const float*)d_in[17];
    const float* b_t1      = (const float*)d_in[18];
    const float* w_t2      = (const float*)d_in[19];
    const float* b_t2      = (const float*)d_in[20];
    float* out = (float*)d_out;

    void *p_hsW, *p_agg, *p_agg_s, *p_counts;
    void *p_WhH, *p_WhL, *p_WhsH, *p_WhsL, *p_WsH, *p_WsL;
    cudaGetSymbolAddress(&p_hsW,    d_hsW);
    cudaGetSymbolAddress(&p_agg,    d_agg);
    cudaGetSymbolAddress(&p_agg_s,  d_agg_s);
    cudaGetSymbolAddress(&p_counts, d_counts);
    cudaGetSymbolAddress(&p_WhH,  d_Wh_hi);
    cudaGetSymbolAddress(&p_WhL,  d_Wh_lo);
    cudaGetSymbolAddress(&p_WhsH, d_Whs_hi);
    cudaGetSymbolAddress(&p_WhsL, d_Whs_lo);
    cudaGetSymbolAddress(&p_WsH,  d_Ws_hi);
    cudaGetSymbolAddress(&p_WsL,  d_Ws_lo);

    const int SMEM128 = 34816 + 2 * 128 * 136 * 2;  // 104448
    const int SMEM64  = 34816 + 2 * 128 * 72 * 2;   //  71680
    cudaFuncSetAttribute(mma_gemm<128>, cudaFuncAttributeMaxDynamicSharedMemorySize, SMEM128);
    cudaFuncSetAttribute(mma_gemm<64>,  cudaFuncAttributeMaxDynamicSharedMemorySize, SMEM64);

    // ---- counting sort of edges by obj ----
    cudaMemsetAsync(p_counts, 0, N_NODE * sizeof(int));
    hist_kernel<<<(N_EDGE + 255) / 256, 256>>>(edges);
    scan1_kernel<<<N_SCANB, SCAN_B>>>();
    scan2_kernel<<<1, 128>>>();
    scan3_kernel<<<N_SCANB, SCAN_B>>>();
    fill_kernel<<<(N_EDGE + 255) / 256, 256>>>(edges);

    // ---- small tables + weight images ----
    table_kernel<<<N_RELTAB + N_Q + N_TAU, 128>>>(rela, q_rel, q_tau, Wr, Wqr, Wqr_b,
                                                  Wtau, w_t1, b_t1, w_t2, b_t2);
    wprep_kernel<<<128, 136>>>(W_h, W_h_s, Ws);

    int gm2 = (N_NODE + 127) / 128;   // 782 (two 64-row tiles per CTA)
    // ---- hsW = hidden @ Ws ----
    mma_gemm<64><<<dim3(gm2, 1), 256, SMEM64>>>(
        hidden, nullptr,
        (const __nv_bfloat16*)p_WsH, (const __nv_bfloat16*)p_WsL,
        nullptr, nullptr,
        (float*)p_hsW, nullptr, N_NODE);
    // ---- attention alphas -> sorted records ----
    int nwarp = (N_EDGE + 1) / 2;
    int nblk  = (nwarp * 32 + 255) / 256;
    alpha_kernel<<<nblk, 256>>>(edges, w_alpha, w_alpha_b, q_tau);
    // ---- sorted aggregation ----
    agg_kernel<<<(N_NODE * 32 + 255) / 256, 256>>>(hidden, rela);
    // ---- output GEMMs (one launch, blockIdx.y selects pair) ----
    mma_gemm<128><<<dim3(gm2, 2), 256, SMEM128>>>(
        (const float*)p_agg, (const float*)p_agg_s,
        (const __nv_bfloat16*)p_WhH, (const __nv_bfloat16*)p_WhL,
        (const __nv_bfloat16*)p_WhsH, (const __nv_bfloat16*)p_WhsL,
        out, out + N_NODE * OUT_DIM, N_NODE);
}